// round 5
// baseline (speedup 1.0000x reference)
#include <cuda_runtime.h>
#include <cstdint>

// Problem constants
#define BB    4096
#define DD    128
#define HIST  50
#define TOPN  4
#define PROTO 1024
#define ITEMS 100000
#define KTOT  1152      // 384 text + 768 visual
#define K1    256       // MLP layer1 input
#define D2    64        // MLP layer2 output
#define ESB   32        // samples per GEMM block
#define CH    32        // K-floats per chunk
#define XPAD  4         // X row padding (floats) to break bank conflicts

typedef unsigned long long ull;

// ---------------- scratch (__device__ globals; no allocation allowed) ----------------
__device__ float2 g_WT2[(KTOT/2)*DD];   // [k2][c] pairs of transposed [Wt|Wv]
__device__ float2 g_PT2[(PROTO/2)*DD];  // [k2][c] pairs of transposed prototypes
__device__ float2 g_W1T2[(K1/2)*DD];
__device__ float2 g_W2T2[(DD/2)*D2];
__device__ float  g_cb[DD];             // bt·Wt_row + bv·Wv_row
__device__ float  g_mask[BB*PROTO];     // 0/1 presence mask (16MB)
__device__ float  g_cinv[BB];           // 1/unique-count
__device__ float  g_IF[BB*K1];          // inter_feat
__device__ float  g_z1[BB*DD];
__device__ float  g_z2[BB*D2];
__device__ float  g_s1[DD], g_q1[DD], g_a1[DD], g_d1[DD];
__device__ float  g_s2[D2], g_q2[D2], g_a2[D2], g_d2[D2];

__device__ __forceinline__ void ffma2(ull &acc, ull a, ull b) {
    asm("fma.rn.f32x2 %0, %1, %2, %0;" : "+l"(acc) : "l"(a), "l"(b));
}
__device__ __forceinline__ float sum2(ull v) {
    return __uint_as_float((unsigned)v) + __uint_as_float((unsigned)(v >> 32));
}
__device__ __forceinline__ void cpa16(void* dst, const void* src) {
    unsigned d = (unsigned)__cvta_generic_to_shared(dst);
    asm volatile("cp.async.cg.shared.global [%0], [%1], 16;" :: "r"(d), "l"(src));
}
__device__ __forceinline__ void cpa_commit() { asm volatile("cp.async.commit_group;"); }
__device__ __forceinline__ void cpa_wait1() { asm volatile("cp.async.wait_group 1;"); }
__device__ __forceinline__ void cpa_wait0() { asm volatile("cp.async.wait_group 0;"); }

// ---------------- prep: transpose weights into k-pair float2 layout + zero stats ----
__global__ void k_prep(const float* __restrict__ Wt, const float* __restrict__ Wv,
                       const float* __restrict__ W1, const float* __restrict__ W2,
                       const float* __restrict__ protos) {
    const int n_wt = (KTOT/2)*DD;       // 73728
    const int n_pt = (PROTO/2)*DD;      // 65536
    const int n_w1 = (K1/2)*DD;         // 16384
    const int n_w2 = (DD/2)*D2;         // 4096
    const int n_z  = 2*DD + 2*D2;
    int total = n_wt + n_pt + n_w1 + n_w2 + n_z;
    for (int i = blockIdx.x*blockDim.x + threadIdx.x; i < total; i += gridDim.x*blockDim.x) {
        if (i < n_wt) {
            int k2 = i / DD, c = i % DD;
            int ka = 2*k2, kb = ka + 1;
            float a = (ka < 384) ? Wt[c*384 + ka] : Wv[c*768 + (ka-384)];
            float b = (kb < 384) ? Wt[c*384 + kb] : Wv[c*768 + (kb-384)];
            g_WT2[i] = make_float2(a, b);
        } else if (i < n_wt + n_pt) {
            int j = i - n_wt; int k2 = j / DD, c = j % DD;
            g_PT2[j] = make_float2(protos[(2*k2)*DD + c], protos[(2*k2+1)*DD + c]);
        } else if (i < n_wt + n_pt + n_w1) {
            int j = i - n_wt - n_pt; int k2 = j / DD, c = j % DD;
            g_W1T2[j] = make_float2(W1[c*K1 + 2*k2], W1[c*K1 + 2*k2 + 1]);
        } else if (i < n_wt + n_pt + n_w1 + n_w2) {
            int j = i - n_wt - n_pt - n_w1; int k2 = j / D2, c = j % D2;
            g_W2T2[j] = make_float2(W2[c*DD + 2*k2], W2[c*DD + 2*k2 + 1]);
        } else {
            int j = i - n_wt - n_pt - n_w1 - n_w2;
            if (j < DD)            g_s1[j] = 0.f;
            else if (j < 2*DD)     g_q1[j-DD] = 0.f;
            else if (j < 2*DD+D2)  g_s2[j-2*DD] = 0.f;
            else                   g_q2[j-2*DD-D2] = 0.f;
        }
    }
}

// cb[c] = bt·Wt[c,:] + bv·Wv[c,:]
__global__ void k_cb(const float* __restrict__ Wt, const float* __restrict__ Wv,
                     const float* __restrict__ bt, const float* __restrict__ bv) {
    int c = blockIdx.x, t = threadIdx.x;
    float s = 0.f;
    for (int k = t; k < 384; k += 256) s += bt[k] * Wt[c*384 + k];
    for (int k = t; k < 768; k += 256) s += bv[k] * Wv[c*768 + k];
    __shared__ float red[256];
    red[t] = s; __syncthreads();
    for (int o = 128; o; o >>= 1) { if (t < o) red[t] += red[t+o]; __syncthreads(); }
    if (t == 0) g_cb[c] = red[0];
}

// ---------------- mask build: bitmask -> dense float mask + counts + prompt gathers --
__global__ void k_mask(const int* __restrict__ nodes_u, const int* __restrict__ nodes_d,
                       const int* __restrict__ inter_items, const int* __restrict__ top_n,
                       const float* __restrict__ up, const float* __restrict__ dp,
                       float* __restrict__ out_pu, float* __restrict__ out_pd) {
    __shared__ unsigned bm[PROTO/32];
    int i = blockIdx.x, tid = threadIdx.x;
    if (tid < 32) bm[tid] = 0u;
    __syncthreads();
    for (int j = tid; j < HIST*8; j += 128) {
        int h = j >> 3, r = j & 7;
        int item = inter_items[i*HIST + h];
        int p = (r < 4) ? top_n[item*TOPN + r] : top_n[(item + ITEMS)*TOPN + (r - 4)];
        atomicOr(&bm[p >> 5], 1u << (p & 31));
    }
    __syncthreads();
    if (tid < 32) {
        unsigned c = __popc(bm[tid]);
        #pragma unroll
        for (int o = 16; o; o >>= 1) c += __shfl_down_sync(0xffffffffu, c, o);
        if (tid == 0) g_cinv[i] = 1.0f / (float)c;
    }
    unsigned w = bm[tid >> 2];
    int sh = (tid & 3) * 8;
    float4 a, b;
    a.x = (w >> (sh+0)) & 1 ? 1.f : 0.f;  a.y = (w >> (sh+1)) & 1 ? 1.f : 0.f;
    a.z = (w >> (sh+2)) & 1 ? 1.f : 0.f;  a.w = (w >> (sh+3)) & 1 ? 1.f : 0.f;
    b.x = (w >> (sh+4)) & 1 ? 1.f : 0.f;  b.y = (w >> (sh+5)) & 1 ? 1.f : 0.f;
    b.z = (w >> (sh+6)) & 1 ? 1.f : 0.f;  b.w = (w >> (sh+7)) & 1 ? 1.f : 0.f;
    float4* mrow = (float4*)&g_mask[(size_t)i*PROTO + tid*8];
    mrow[0] = a; mrow[1] = b;
    out_pu[i*DD + tid] = up[nodes_u[i]*DD + tid];
    out_pd[i*DD + tid] = dp[nodes_d[i]*DD + tid];
}

// ===================================================================================
// Big-GEMM tile (512 threads, 32 samples x 128 cols, grid=128, 3-stage pipeline,
// ONE barrier per chunk):
//   warp w in [0,16); lane: sg = lane>>2 in [0,8), cgl = lane&3; cg = w*4+cgl
//   thread tile: cols 2cg,2cg+1 x samples {i*8+sg : i in [0,4)}  (8 accumulators)
//   W chunk smem: [16 k2][64 cg] x 16B = 16KB x3 ; X chunk: [32 samp][36 f] x3
// Pipeline per chunk: wait_group -> ONE syncthreads -> compute(ch) -> stage(ch+2)
//   (stage-after-compute: sync(iter ch) proves compute(ch-1) done in all threads,
//    and that is the only reader of the buffer stage(ch+2) overwrites)
// ===================================================================================
#define GEMM_CORE(Wb_, Xb_, bsel)                                              \
    _Pragma("unroll")                                                          \
    for (int p2 = 0; p2 < 8; ++p2) {                                           \
        ulonglong2 w0 = Wb_[bsel][(2*p2)*64 + cg];                             \
        ulonglong2 w1 = Wb_[bsel][(2*p2+1)*64 + cg];                           \
        _Pragma("unroll")                                                      \
        for (int i = 0; i < 4; ++i) {                                          \
            ulonglong2 x = *(const ulonglong2*)&Xb_[bsel][i*8 + sg][4*p2];     \
            ffma2(acc[i][0], w0.x, x.x);                                       \
            ffma2(acc[i][1], w0.y, x.x);                                       \
            ffma2(acc[i][0], w1.x, x.y);                                       \
            ffma2(acc[i][1], w1.y, x.y);                                       \
        }                                                                      \
    }

// ---------------- h_u GEMM: h_u = (mask @ protos)*cinv ; IF[:,0:128] = h_u + p_d ----
__global__ void __launch_bounds__(512) k_hu(const int* __restrict__ nodes_d,
                                            const float* __restrict__ dp,
                                            float* __restrict__ out_hu) {
    __shared__ __align__(16) ulonglong2 Wb[3][16*64];
    __shared__ __align__(16) float Xb[3][ESB][CH+XPAD];
    int blk = blockIdx.x, tid = threadIdx.x;
    int w = tid >> 5, lane = tid & 31;
    int sg = lane >> 2, cgl = lane & 3, cg = w*4 + cgl;
    int c0 = cg*2;
    int xs = tid >> 3, xj = tid & 7;   // X staging role (tid<256)

    auto stage = [&](int ch, int b) {
        const float4* wsrc = (const float4*)(g_PT2 + (ch*(CH/2))*DD);
        const float4* wdst = (const float4*)Wb[b];
        cpa16((void*)(wdst + tid*2),     wsrc + tid*2);
        cpa16((void*)(wdst + tid*2 + 1), wsrc + tid*2 + 1);
        if (tid < 256)
            cpa16(&Xb[b][xs][xj*4],
                  &g_mask[(size_t)(blk*ESB + xs)*PROTO + ch*CH + xj*4]);
        cpa_commit();
    };

    ull acc[4][2];
    #pragma unroll
    for (int i = 0; i < 4; ++i) { acc[i][0] = 0ull; acc[i][1] = 0ull; }

    const int NCH = PROTO/CH;   // 32
    stage(0, 0); stage(1, 1);
    #pragma unroll 1
    for (int ch = 0; ch < NCH; ++ch) {
        if (ch + 1 < NCH) cpa_wait1(); else cpa_wait0();
        __syncthreads();
        GEMM_CORE(Wb, Xb, ch % 3);
        if (ch + 2 < NCH) stage(ch + 2, (ch + 2) % 3);
    }
    #pragma unroll
    for (int i = 0; i < 4; ++i) {
        int s = blk*ESB + i*8 + sg;
        float inv = g_cinv[s];
        int nd = nodes_d[s];
        float h0 = sum2(acc[i][0]) * inv;
        float h1 = sum2(acc[i][1]) * inv;
        *(float2*)&out_hu[s*DD + c0] = make_float2(h0, h1);
        float2 pd = *(const float2*)&dp[nd*DD + c0];
        *(float2*)&g_IF[s*K1 + c0] = make_float2(h0 + pd.x, h1 + pd.y);
    }
}

// ---------------- e_i_hat GEMM: (x-b)@[Wt|Wv]^T + item_prompt -> IF[:,128:256] ------
__global__ void __launch_bounds__(512) k_e(
        const int* __restrict__ nodes_v, const float* __restrict__ pre_text,
        const float* __restrict__ pre_visual, const float* __restrict__ ip) {
    __shared__ int svs[ESB];
    __shared__ __align__(16) ulonglong2 Wb[3][16*64];
    __shared__ __align__(16) float Xb[3][ESB][CH+XPAD];
    int blk = blockIdx.x, tid = threadIdx.x;
    int w = tid >> 5, lane = tid & 31;
    int sg = lane >> 2, cgl = lane & 3, cg = w*4 + cgl;
    int c0 = cg*2;
    if (tid < ESB) svs[tid] = nodes_v[blk*ESB + tid];
    __syncthreads();
    int xs = tid >> 3, xj = tid & 7;
    int xrow = (tid < 256) ? svs[xs] : 0;

    auto stage = [&](int ch, int b) {
        int k0 = ch * CH;
        const float4* wsrc = (const float4*)(g_WT2 + (k0 >> 1)*DD);
        const float4* wdst = (const float4*)Wb[b];
        cpa16((void*)(wdst + tid*2),     wsrc + tid*2);
        cpa16((void*)(wdst + tid*2 + 1), wsrc + tid*2 + 1);
        if (tid < 256) {
            const float* src = (k0 < 384) ? (pre_text + (size_t)xrow*384 + k0)
                                          : (pre_visual + (size_t)xrow*768 + (k0 - 384));
            cpa16(&Xb[b][xs][xj*4], src + xj*4);
        }
        cpa_commit();
    };

    ull acc[4][2];
    #pragma unroll
    for (int i = 0; i < 4; ++i) { acc[i][0] = 0ull; acc[i][1] = 0ull; }

    const int NCH = KTOT/CH;    // 36
    stage(0, 0); stage(1, 1);
    #pragma unroll 1
    for (int ch = 0; ch < NCH; ++ch) {
        if (ch + 1 < NCH) cpa_wait1(); else cpa_wait0();
        __syncthreads();
        GEMM_CORE(Wb, Xb, ch % 3);
        if (ch + 2 < NCH) stage(ch + 2, (ch + 2) % 3);
    }
    float2 cbv = *(const float2*)&g_cb[c0];
    #pragma unroll
    for (int i = 0; i < 4; ++i) {
        int sl = i*8 + sg;
        int s = blk*ESB + sl;
        float2 ipv = *(const float2*)&ip[(size_t)svs[sl]*DD + c0];
        float e0 = sum2(acc[i][0]) - cbv.x + ipv.x;
        float e1 = sum2(acc[i][1]) - cbv.y + ipv.y;
        *(float2*)&g_IF[s*K1 + DD + c0] = make_float2(e0, e1);
    }
}

// ---------------- z1 = relu(IF @ W1^T + b1) + partial BN stats ---------------------
__global__ void __launch_bounds__(512) k_z1(const float* __restrict__ b1) {
    __shared__ __align__(16) ulonglong2 Wb[3][16*64];
    __shared__ __align__(16) float Xb[3][ESB][CH+XPAD];
    int blk = blockIdx.x, tid = threadIdx.x;
    int w = tid >> 5, lane = tid & 31;
    int sg = lane >> 2, cgl = lane & 3, cg = w*4 + cgl;
    int c0 = cg*2;
    int xs = tid >> 3, xj = tid & 7;

    auto stage = [&](int ch, int b) {
        const float4* wsrc = (const float4*)(g_W1T2 + (ch*(CH/2))*DD);
        const float4* wdst = (const float4*)Wb[b];
        cpa16((void*)(wdst + tid*2),     wsrc + tid*2);
        cpa16((void*)(wdst + tid*2 + 1), wsrc + tid*2 + 1);
        if (tid < 256)
            cpa16(&Xb[b][xs][xj*4], &g_IF[(blk*ESB + xs)*K1 + ch*CH + xj*4]);
        cpa_commit();
    };

    ull acc[4][2];
    #pragma unroll
    for (int i = 0; i < 4; ++i) { acc[i][0] = 0ull; acc[i][1] = 0ull; }

    const int NCH = K1/CH;  // 8
    stage(0, 0); stage(1, 1);
    #pragma unroll 1
    for (int ch = 0; ch < NCH; ++ch) {
        if (ch + 1 < NCH) cpa_wait1(); else cpa_wait0();
        __syncthreads();
        GEMM_CORE(Wb, Xb, ch % 3);
        if (ch + 2 < NCH) stage(ch + 2, (ch + 2) % 3);
    }
    float2 bb = *(const float2*)&b1[c0];
    float s0 = 0.f, s1 = 0.f, q0 = 0.f, q1 = 0.f;
    #pragma unroll
    for (int i = 0; i < 4; ++i) {
        int s = blk*ESB + i*8 + sg;
        float z0 = sum2(acc[i][0]) + bb.x;  z0 = z0 > 0.f ? z0 : 0.f;
        float z1v = sum2(acc[i][1]) + bb.y; z1v = z1v > 0.f ? z1v : 0.f;
        *(float2*)&g_z1[s*DD + c0] = make_float2(z0, z1v);
        s0 += z0; s1 += z1v; q0 += z0*z0; q1 += z1v*z1v;
    }
    // reduce across sg (lane bits 2..4), then one atomic per column pair
    #pragma unroll
    for (int o = 4; o <= 16; o <<= 1) {
        s0 += __shfl_xor_sync(0xffffffffu, s0, o);
        s1 += __shfl_xor_sync(0xffffffffu, s1, o);
        q0 += __shfl_xor_sync(0xffffffffu, q0, o);
        q1 += __shfl_xor_sync(0xffffffffu, q1, o);
    }
    if (sg == 0) {
        atomicAdd(&g_s1[c0], s0);   atomicAdd(&g_s1[c0+1], s1);
        atomicAdd(&g_q1[c0], q0);   atomicAdd(&g_q1[c0+1], q1);
    }
}

__global__ void k_m1(const float* __restrict__ g1, const float* __restrict__ be1) {
    int c = threadIdx.x;  // 128
    float m = g_s1[c] * (1.0f/BB);
    float v = g_q1[c] * (1.0f/BB) - m*m;
    float r = rsqrtf(v + 1e-5f);
    float a = g1[c] * r;
    g_a1[c] = a;
    g_d1[c] = be1[c] - m*a;
}

// ---------------- z2 = relu(BN(z1) @ W2^T + b2) + partial BN stats -----------------
// 256 threads, 32 samples, grid=128: c = tid&63 (col), h = tid>>6 (sample quarter)
__global__ void __launch_bounds__(256) k_z2(const float* __restrict__ b2) {
    __shared__ __align__(16) float2 W2s[(DD/2)*D2];  // 32KB
    __shared__ __align__(16) float X[ESB][DD];       // 16KB
    __shared__ float A1[DD], D1[DD];
    int blk = blockIdx.x, tid = threadIdx.x;
    int c = tid & 63, h = tid >> 6;
    if (tid < DD) { A1[tid] = g_a1[tid]; D1[tid] = g_d1[tid]; }
    {
        const float4* src = (const float4*)g_W2T2;
        float4* dst = (float4*)W2s;
        #pragma unroll
        for (int i = 0; i < 8; ++i)
            cpa16(dst + tid + i*256, src + tid + i*256);
        cpa_commit();
    }
    __syncthreads();
    for (int l = tid; l < ESB*DD; l += 256) {
        int s = l >> 7, kk = l & 127;
        X[s][kk] = g_z1[(blk*ESB + s)*DD + kk] * A1[kk] + D1[kk];
    }
    cpa_wait0();
    __syncthreads();
    ull acc[8];
    #pragma unroll
    for (int i = 0; i < 8; ++i) acc[i] = 0ull;
    #pragma unroll 8
    for (int p = 0; p < DD/2; ++p) {
        ull wv = *(const ull*)&W2s[p*D2 + c];
        #pragma unroll
        for (int i = 0; i < 8; ++i) {
            ull x = *(const ull*)&X[h*8 + i][2*p];
            ffma2(acc[i], wv, x);
        }
    }
    float bb = b2[c];
    float lsum = 0.f, lss = 0.f;
    #pragma unroll
    for (int i = 0; i < 8; ++i) {
        float z = sum2(acc[i]) + bb;
        z = z > 0.f ? z : 0.f;
        g_z2[(blk*ESB + h*8 + i)*D2 + c] = z;
        lsum += z; lss += z*z;
    }
    atomicAdd(&g_s2[c], lsum);
    atomicAdd(&g_q2[c], lss);
}

__global__ void k_m2(const float* __restrict__ g2, const float* __restrict__ be2) {
    int c = threadIdx.x;  // 64
    float m = g_s2[c] * (1.0f/BB);
    float v = g_q2[c] * (1.0f/BB) - m*m;
    float r = rsqrtf(v + 1e-5f);
    float a = g2[c] * r;
    g_a2[c] = a;
    g_d2[c] = be2[c] - m*a;
}

// ---------------- pred = sigmoid(BN(z2) @ Wp^T + bp) -------------------------------
__global__ void k_pred(const float* __restrict__ Wp, const float* __restrict__ bp,
                       float* __restrict__ out_pred) {
    int warp = (blockIdx.x*blockDim.x + threadIdx.x) >> 5;
    int lane = threadIdx.x & 31;
    if (warp >= BB) return;
    float t = 0.f;
    #pragma unroll
    for (int j = 0; j < 2; ++j) {
        int cidx = lane + j*32;
        float f2 = g_z2[warp*D2 + cidx] * g_a2[cidx] + g_d2[cidx];
        t += f2 * Wp[cidx];
    }
    #pragma unroll
    for (int o = 16; o; o >>= 1) t += __shfl_down_sync(0xffffffffu, t, o);
    if (lane == 0) out_pred[warp] = 1.0f / (1.0f + expf(-(t + bp[0])));
}

// ---------------- launch ------------------------------------------------------------
extern "C" void kernel_launch(void* const* d_in, const int* in_sizes, int n_in,
                              void* d_out, int out_size) {
    const int*   nodes_u     = (const int*)  d_in[0];
    const int*   nodes_v     = (const int*)  d_in[1];
    const int*   nodes_d     = (const int*)  d_in[2];
    const int*   inter_items = (const int*)  d_in[3];
    const int*   top_n       = (const int*)  d_in[4];
    const float* protos      = (const float*)d_in[5];
    const float* pre_text    = (const float*)d_in[6];
    const float* pre_visual  = (const float*)d_in[7];
    const float* Wt          = (const float*)d_in[8];
    const float* bt          = (const float*)d_in[9];
    const float* Wv          = (const float*)d_in[10];
    const float* bv          = (const float*)d_in[11];
    const float* up          = (const float*)d_in[12];
    const float* ip          = (const float*)d_in[13];
    const float* dp          = (const float*)d_in[14];
    const float* W1          = (const float*)d_in[15];
    const float* b1          = (const float*)d_in[16];
    const float* g1          = (const float*)d_in[17];
    const float* be1         = (const float*)d_in[18];
    const float* W2          = (const float*)d_in[19];
    const float* b2          = (const float*)d_in[20];
    const float* g2          = (const float*)d_in[21];
    const float* be2         = (const float*)d_in[22];
    const float* Wp          = (const float*)d_in[23];
    const float* bp          = (const float*)d_in[24];

    float* out      = (float*)d_out;
    float* out_pred = out;
    float* out_pu   = out + BB;
    float* out_hu   = out + BB + BB*DD;
    float* out_pd   = out + BB + 2*BB*DD;

    k_prep<<<296, 256>>>(Wt, Wv, W1, W2, protos);
    k_cb<<<DD, 256>>>(Wt, Wv, bt, bv);
    k_mask<<<BB, 128>>>(nodes_u, nodes_d, inter_items, top_n, up, dp, out_pu, out_pd);
    k_e<<<BB/ESB, 512>>>(nodes_v, pre_text, pre_visual, ip);
    k_hu<<<BB/ESB, 512>>>(nodes_d, dp, out_hu);
    k_z1<<<BB/ESB, 512>>>(b1);
    k_m1<<<1, 128>>>(g1, be1);
    k_z2<<<BB/ESB, 256>>>(b2);
    k_m2<<<1, 64>>>(g2, be2);
    k_pred<<<BB/8, 256>>>(Wp, bp, out_pred);
}

// round 7
// speedup vs baseline: 1.2257x; 1.2257x over previous
#include <cuda_runtime.h>
#include <cuda_bf16.h>
#include <cstdint>

// Problem constants
#define BB    4096
#define DD    128
#define HIST  50
#define TOPN  4
#define PROTO 1024
#define ITEMS 100000
#define KTOT  1152      // 384 text + 768 visual
#define K1    256       // MLP layer1 input
#define D2    64        // MLP layer2 output
#define ESB   32        // samples per FFMA2-GEMM block
#define ESG   16        // samples per z2 block
#define CH    32        // K-floats per chunk
#define XPAD  4

typedef unsigned long long ull;

// ---------------- scratch (__device__ globals; no allocation allowed) ----------------
__device__ float2 g_WT2[(KTOT/2)*DD];   // [k2][c] pairs of transposed [Wt|Wv]
__device__ float2 g_W1T2[(K1/2)*DD];
__device__ float2 g_W2T2[(DD/2)*D2];
__device__ float  g_cb[DD];             // bt·Wt_row + bv·Wv_row
__device__ uint4  g_maskh4[BB*PROTO/8]; // bf16 0/1 presence mask (8MB)
__device__ __align__(16) __nv_bfloat16 g_PB2[2*128*1024]; // 2-way bf16 split of protos^T [split][c][k]
__device__ float  g_cinv[BB];           // 1/unique-count
__device__ float  g_IF[BB*K1];          // inter_feat
__device__ float  g_z1[BB*DD];
__device__ float  g_z2[BB*D2];
__device__ float  g_s1[DD], g_q1[DD], g_a1[DD], g_d1[DD];
__device__ float  g_s2[D2], g_q2[D2], g_a2[D2], g_d2[D2];

__device__ __forceinline__ void ffma2(ull &acc, ull a, ull b) {
    asm("fma.rn.f32x2 %0, %1, %2, %0;" : "+l"(acc) : "l"(a), "l"(b));
}
__device__ __forceinline__ float sum2(ull v) {
    return __uint_as_float((unsigned)v) + __uint_as_float((unsigned)(v >> 32));
}
__device__ __forceinline__ void cpa16(void* dst, const void* src) {
    unsigned d = (unsigned)__cvta_generic_to_shared(dst);
    asm volatile("cp.async.cg.shared.global [%0], [%1], 16;" :: "r"(d), "l"(src));
}
__device__ __forceinline__ void cpa_commit() { asm volatile("cp.async.commit_group;"); }
__device__ __forceinline__ void cpa_wait1() { asm volatile("cp.async.wait_group 1;"); }
__device__ __forceinline__ void cpa_wait0() { asm volatile("cp.async.wait_group 0;"); }

// HMMA bf16: D(f32) += A(bf16 m16k16 row) * B(bf16 k16n8 col)
__device__ __forceinline__ void mma_bf16(float* d, uint32_t a0, uint32_t a1,
                                         uint32_t a2, uint32_t a3,
                                         uint32_t b0, uint32_t b1) {
    asm volatile("mma.sync.aligned.m16n8k16.row.col.f32.bf16.bf16.f32 "
                 "{%0,%1,%2,%3},{%4,%5,%6,%7},{%8,%9},{%0,%1,%2,%3};"
                 : "+f"(d[0]), "+f"(d[1]), "+f"(d[2]), "+f"(d[3])
                 : "r"(a0), "r"(a1), "r"(a2), "r"(a3), "r"(b0), "r"(b1));
}

// ---------------- prep: transposed weight layouts + bf16 proto split + zero stats ---
__global__ void k_prep(const float* __restrict__ Wt, const float* __restrict__ Wv,
                       const float* __restrict__ W1, const float* __restrict__ W2,
                       const float* __restrict__ protos) {
    const int n_wt = (KTOT/2)*DD;       // 73728
    const int n_pb = 128*1024;          // 131072 proto elements (2 split outputs each)
    const int n_w1 = (K1/2)*DD;         // 16384
    const int n_w2 = (DD/2)*D2;         // 4096
    const int n_z  = 2*DD + 2*D2;
    int total = n_wt + n_pb + n_w1 + n_w2 + n_z;
    for (int i = blockIdx.x*blockDim.x + threadIdx.x; i < total; i += gridDim.x*blockDim.x) {
        if (i < n_wt) {
            int k2 = i / DD, c = i % DD;
            int ka = 2*k2, kb = ka + 1;
            float a = (ka < 384) ? Wt[c*384 + ka] : Wv[c*768 + (ka-384)];
            float b = (kb < 384) ? Wt[c*384 + kb] : Wv[c*768 + (kb-384)];
            g_WT2[i] = make_float2(a, b);
        } else if (i < n_wt + n_pb) {
            int j = i - n_wt; int c = j & 127; int k = j >> 7;
            float p = protos[k*DD + c];
            __nv_bfloat16 b1 = __float2bfloat16(p);
            float r1 = p - __bfloat162float(b1);
            g_PB2[c*1024 + k]          = b1;
            g_PB2[131072 + c*1024 + k] = __float2bfloat16(r1);
        } else if (i < n_wt + n_pb + n_w1) {
            int j = i - n_wt - n_pb; int k2 = j / DD, c = j % DD;
            g_W1T2[j] = make_float2(W1[c*K1 + 2*k2], W1[c*K1 + 2*k2 + 1]);
        } else if (i < n_wt + n_pb + n_w1 + n_w2) {
            int j = i - n_wt - n_pb - n_w1; int k2 = j / D2, c = j % D2;
            g_W2T2[j] = make_float2(W2[c*DD + 2*k2], W2[c*DD + 2*k2 + 1]);
        } else {
            int j = i - n_wt - n_pb - n_w1 - n_w2;
            if (j < DD)            g_s1[j] = 0.f;
            else if (j < 2*DD)     g_q1[j-DD] = 0.f;
            else if (j < 2*DD+D2)  g_s2[j-2*DD] = 0.f;
            else                   g_q2[j-2*DD-D2] = 0.f;
        }
    }
}

// cb[c] = bt·Wt[c,:] + bv·Wv[c,:]
__global__ void k_cb(const float* __restrict__ Wt, const float* __restrict__ Wv,
                     const float* __restrict__ bt, const float* __restrict__ bv) {
    int c = blockIdx.x, t = threadIdx.x;
    float s = 0.f;
    for (int k = t; k < 384; k += 256) s += bt[k] * Wt[c*384 + k];
    for (int k = t; k < 768; k += 256) s += bv[k] * Wv[c*768 + k];
    __shared__ float red[256];
    red[t] = s; __syncthreads();
    for (int o = 128; o; o >>= 1) { if (t < o) red[t] += red[t+o]; __syncthreads(); }
    if (t == 0) g_cb[c] = red[0];
}

// ---------------- mask build: bitmask -> bf16 mask + counts + prompt gathers --------
__global__ void k_mask(const int* __restrict__ nodes_u, const int* __restrict__ nodes_d,
                       const int* __restrict__ inter_items, const int* __restrict__ top_n,
                       const float* __restrict__ up, const float* __restrict__ dp,
                       float* __restrict__ out_pu, float* __restrict__ out_pd) {
    __shared__ unsigned bm[PROTO/32];
    int i = blockIdx.x, tid = threadIdx.x;
    if (tid < 32) bm[tid] = 0u;
    __syncthreads();
    for (int j = tid; j < HIST*8; j += 128) {
        int h = j >> 3, r = j & 7;
        int item = inter_items[i*HIST + h];
        int p = (r < 4) ? top_n[item*TOPN + r] : top_n[(item + ITEMS)*TOPN + (r - 4)];
        atomicOr(&bm[p >> 5], 1u << (p & 31));
    }
    __syncthreads();
    if (tid < 32) {
        unsigned c = __popc(bm[tid]);
        #pragma unroll
        for (int o = 16; o; o >>= 1) c += __shfl_down_sync(0xffffffffu, c, o);
        if (tid == 0) g_cinv[i] = 1.0f / (float)c;
    }
    unsigned w = bm[tid >> 2];
    int sh = (tid & 3) * 8;
    uint32_t pk[4];
    #pragma unroll
    for (int q = 0; q < 4; ++q) {
        uint32_t lo = ((w >> (sh + 2*q)) & 1) ? 0x3F80u : 0u;
        uint32_t hi = ((w >> (sh + 2*q + 1)) & 1) ? 0x3F80u : 0u;
        pk[q] = lo | (hi << 16);
    }
    g_maskh4[(size_t)i*128 + tid] = make_uint4(pk[0], pk[1], pk[2], pk[3]);
    out_pu[i*DD + tid] = up[nodes_u[i]*DD + tid];
    out_pd[i*DD + tid] = dp[nodes_d[i]*DD + tid];
}

// ---------------- h_u via mma.sync bf16: D = mask @ (B1 | B2 stacked in K) ----------
// 128 CTAs x 256 thr; per CTA M=32 samples, N=128 cols, K_ext=2048 in 32 chunks of 64.
// Warp w covers cols [w*16, w*16+16). Per-warp frags: 2(m16) x 2(n8) x 4 f32.
// smem row stride 72 bf16 (144B) -> conflict-free LDS.32 fragment loads.
#define HU_BK   64
#define HU_ST   72
#define HU_ABUF (32*HU_ST*2)        // 4608 B
#define HU_BBUF (128*HU_ST*2)       // 18432 B
#define HU_BUF  (HU_ABUF + HU_BBUF) // 23040 B
#define HU_SMEM (3*HU_BUF)          // 69120 B

__global__ void __launch_bounds__(256) k_hu_mma(const int* __restrict__ nodes_d,
                                                const float* __restrict__ dp,
                                                float* __restrict__ out_hu) {
    extern __shared__ char sm[];
    int blk = blockIdx.x, tid = threadIdx.x;
    int w = tid >> 5, lane = tid & 31;
    int gr = lane >> 2, kb = (lane & 3) * 2;

    auto stage = [&](int ch, int b) {
        char* Ad = sm + b*HU_BUF;
        char* Bd = Ad + HU_ABUF;
        int k0 = ch * HU_BK;
        int split = k0 >> 10, kk = k0 & 1023;
        // A: 32 rows x 128B  (256 x 16B transfers, 1/thread)
        const char* asrc = (const char*)g_maskh4
                         + (size_t)(blk*32 + (tid >> 3))*2048 + kk*2 + (tid & 7)*16;
        cpa16(Ad + (tid >> 3)*144 + (tid & 7)*16, asrc);
        // B: 128 cols x 128B (1024 x 16B transfers, 4/thread)
        const char* bbase = (const char*)g_PB2 + ((size_t)split << 18);
        #pragma unroll
        for (int i = 0; i < 4; ++i) {
            int idx = tid + i*256; int c = idx >> 3, pc = idx & 7;
            cpa16(Bd + c*144 + pc*16, bbase + (size_t)c*2048 + kk*2 + pc*16);
        }
        cpa_commit();
    };

    float d[2][2][4];
    #pragma unroll
    for (int mi = 0; mi < 2; ++mi)
        #pragma unroll
        for (int ni = 0; ni < 2; ++ni)
            #pragma unroll
            for (int q = 0; q < 4; ++q) d[mi][ni][q] = 0.f;

    const int NCH = 2048/HU_BK;   // 32
    stage(0, 0); stage(1, 1);
    #pragma unroll 1
    for (int ch = 0; ch < NCH; ++ch) {
        __syncthreads();
        if (ch + 2 < NCH) stage(ch + 2, (ch + 2) % 3);
        if (ch + 2 < NCH) { asm volatile("cp.async.wait_group 2;"); }
        else if (ch + 1 < NCH) cpa_wait1();
        else cpa_wait0();
        __syncthreads();
        const __nv_bfloat16* A = (const __nv_bfloat16*)(sm + (ch % 3)*HU_BUF);
        const __nv_bfloat16* B = (const __nv_bfloat16*)(sm + (ch % 3)*HU_BUF + HU_ABUF);
        #pragma unroll
        for (int ks = 0; ks < HU_BK/16; ++ks) {
            int k = ks*16 + kb;
            #pragma unroll
            for (int mi = 0; mi < 2; ++mi) {
                int r0 = mi*16 + gr;
                uint32_t a0 = *(const uint32_t*)&A[r0*HU_ST + k];
                uint32_t a1 = *(const uint32_t*)&A[(r0+8)*HU_ST + k];
                uint32_t a2 = *(const uint32_t*)&A[r0*HU_ST + k + 8];
                uint32_t a3 = *(const uint32_t*)&A[(r0+8)*HU_ST + k + 8];
                #pragma unroll
                for (int ni = 0; ni < 2; ++ni) {
                    int n = w*16 + ni*8 + gr;
                    uint32_t b0 = *(const uint32_t*)&B[n*HU_ST + k];
                    uint32_t b1 = *(const uint32_t*)&B[n*HU_ST + k + 8];
                    mma_bf16(d[mi][ni], a0, a1, a2, a3, b0, b1);
                }
            }
        }
    }
    // epilogue: scale by cinv, add p_d into IF, write out_hu
    #pragma unroll
    for (int mi = 0; mi < 2; ++mi) {
        #pragma unroll
        for (int rr = 0; rr < 2; ++rr) {
            int s = blk*32 + mi*16 + gr + rr*8;
            float inv = g_cinv[s];
            const float* pdr = dp + nodes_d[s]*DD;
            #pragma unroll
            for (int ni = 0; ni < 2; ++ni) {
                int c = w*16 + ni*8 + (lane & 3)*2;
                float h0 = d[mi][ni][rr*2]   * inv;
                float h1 = d[mi][ni][rr*2+1] * inv;
                *(float2*)&out_hu[s*DD + c] = make_float2(h0, h1);
                float2 pd = *(const float2*)&pdr[c];
                *(float2*)&g_IF[s*K1 + c] = make_float2(h0 + pd.x, h1 + pd.y);
            }
        }
    }
}

// ===================================================================================
// FFMA2 GEMM tile (R4 config: 256 threads, 32 samples, grid=128, 3-stage pipeline)
// ===================================================================================
#define GEMM_CORE(Wb_, Xb_, bsel)                                              \
    _Pragma("unroll")                                                          \
    for (int p2 = 0; p2 < 8; ++p2) {                                           \
        ulonglong2 w0 = Wb_[bsel][(2*p2)*64 + cg];                             \
        ulonglong2 w1 = Wb_[bsel][(2*p2+1)*64 + cg];                           \
        _Pragma("unroll")                                                      \
        for (int i = 0; i < 8; ++i) {                                          \
            ulonglong2 x = *(const ulonglong2*)&Xb_[bsel][i*4 + sg][4*p2];     \
            ffma2(acc[i][0], w0.x, x.x);                                       \
            ffma2(acc[i][1], w0.y, x.x);                                       \
            ffma2(acc[i][0], w1.x, x.y);                                       \
            ffma2(acc[i][1], w1.y, x.y);                                       \
        }                                                                      \
    }

#define PIPE_WAIT(ch_, nch_)                                                   \
    if ((ch_) + 2 < (nch_)) { asm volatile("cp.async.wait_group 2;"); }        \
    else if ((ch_) + 1 < (nch_)) cpa_wait1();                                  \
    else cpa_wait0();

// ---------------- e_i_hat GEMM: (x-b)@[Wt|Wv]^T + item_prompt -> IF[:,128:256] ------
__global__ void __launch_bounds__(256) k_e(
        const int* __restrict__ nodes_v, const float* __restrict__ pre_text,
        const float* __restrict__ pre_visual, const float* __restrict__ ip) {
    __shared__ int svs[ESB];
    __shared__ __align__(16) ulonglong2 Wb[3][16*64];
    __shared__ __align__(16) float Xb[3][ESB][CH+XPAD];
    int blk = blockIdx.x, tid = threadIdx.x;
    int w = tid >> 5, lane = tid & 31;
    int sg = lane >> 3, cgl = lane & 7, cg = w*8 + cgl;
    int c0 = cg*2;
    if (tid < ESB) svs[tid] = nodes_v[blk*ESB + tid];
    __syncthreads();
    int xs = tid >> 3, xj = tid & 7;
    int xrow = svs[xs];

    auto stage = [&](int ch, int b) {
        int k0 = ch * CH;
        const float4* wsrc = (const float4*)(g_WT2 + (k0 >> 1)*DD);
        const float4* wdst = (const float4*)Wb[b];
        #pragma unroll
        for (int i = 0; i < 4; ++i)
            cpa16((void*)(wdst + tid*4 + i), wsrc + tid*4 + i);
        const float* src = (k0 < 384) ? (pre_text + (size_t)xrow*384 + k0)
                                      : (pre_visual + (size_t)xrow*768 + (k0 - 384));
        cpa16(&Xb[b][xs][xj*4], src + xj*4);
        cpa_commit();
    };

    ull acc[8][2];
    #pragma unroll
    for (int i = 0; i < 8; ++i) { acc[i][0] = 0ull; acc[i][1] = 0ull; }

    const int NCH = KTOT/CH;    // 36
    stage(0, 0); stage(1, 1);
    #pragma unroll 1
    for (int ch = 0; ch < NCH; ++ch) {
        __syncthreads();
        if (ch + 2 < NCH) stage(ch + 2, (ch + 2) % 3);
        PIPE_WAIT(ch, NCH);
        __syncthreads();
        GEMM_CORE(Wb, Xb, ch % 3);
    }
    float2 cbv = *(const float2*)&g_cb[c0];
    #pragma unroll
    for (int i = 0; i < 8; ++i) {
        int sl = i*4 + sg;
        int s = blk*ESB + sl;
        float2 ipv = *(const float2*)&ip[(size_t)svs[sl]*DD + c0];
        float e0 = sum2(acc[i][0]) - cbv.x + ipv.x;
        float e1 = sum2(acc[i][1]) - cbv.y + ipv.y;
        *(float2*)&g_IF[s*K1 + DD + c0] = make_float2(e0, e1);
    }
}

// ---------------- z1 = relu(IF @ W1^T + b1) + partial BN stats ---------------------
__global__ void __launch_bounds__(256) k_z1(const float* __restrict__ b1) {
    __shared__ __align__(16) ulonglong2 Wb[3][16*64];
    __shared__ __align__(16) float Xb[3][ESB][CH+XPAD];
    int blk = blockIdx.x, tid = threadIdx.x;
    int w = tid >> 5, lane = tid & 31;
    int sg = lane >> 3, cgl = lane & 7, cg = w*8 + cgl;
    int c0 = cg*2;
    int xs = tid >> 3, xj = tid & 7;

    auto stage = [&](int ch, int b) {
        const float4* wsrc = (const float4*)(g_W1T2 + (ch*(CH/2))*DD);
        const float4* wdst = (const float4*)Wb[b];
        #pragma unroll
        for (int i = 0; i < 4; ++i)
            cpa16((void*)(wdst + tid*4 + i), wsrc + tid*4 + i);
        cpa16(&Xb[b][xs][xj*4], &g_IF[(blk*ESB + xs)*K1 + ch*CH + xj*4]);
        cpa_commit();
    };

    ull acc[8][2];
    #pragma unroll
    for (int i = 0; i < 8; ++i) { acc[i][0] = 0ull; acc[i][1] = 0ull; }

    const int NCH = K1/CH;  // 8
    stage(0, 0); stage(1, 1);
    #pragma unroll 1
    for (int ch = 0; ch < NCH; ++ch) {
        __syncthreads();
        if (ch + 2 < NCH) stage(ch + 2, (ch + 2) % 3);
        PIPE_WAIT(ch, NCH);
        __syncthreads();
        GEMM_CORE(Wb, Xb, ch % 3);
    }
    float2 bb = *(const float2*)&b1[c0];
    float s0 = 0.f, s1 = 0.f, q0 = 0.f, q1 = 0.f;
    #pragma unroll
    for (int i = 0; i < 8; ++i) {
        int s = blk*ESB + i*4 + sg;
        float z0 = sum2(acc[i][0]) + bb.x;  z0 = z0 > 0.f ? z0 : 0.f;
        float z1v = sum2(acc[i][1]) + bb.y; z1v = z1v > 0.f ? z1v : 0.f;
        *(float2*)&g_z1[s*DD + c0] = make_float2(z0, z1v);
        s0 += z0; s1 += z1v; q0 += z0*z0; q1 += z1v*z1v;
    }
    #pragma unroll
    for (int o = 8; o <= 16; o <<= 1) {
        s0 += __shfl_xor_sync(0xffffffffu, s0, o);
        s1 += __shfl_xor_sync(0xffffffffu, s1, o);
        q0 += __shfl_xor_sync(0xffffffffu, q0, o);
        q1 += __shfl_xor_sync(0xffffffffu, q1, o);
    }
    if (sg == 0) {
        atomicAdd(&g_s1[c0], s0);   atomicAdd(&g_s1[c0+1], s1);
        atomicAdd(&g_q1[c0], q0);   atomicAdd(&g_q1[c0+1], q1);
    }
}

__global__ void k_m1(const float* __restrict__ g1, const float* __restrict__ be1) {
    int c = threadIdx.x;  // 128
    float m = g_s1[c] * (1.0f/BB);
    float v = g_q1[c] * (1.0f/BB) - m*m;
    float r = rsqrtf(v + 1e-5f);
    float a = g1[c] * r;
    g_a1[c] = a;
    g_d1[c] = be1[c] - m*a;
}

// ---------------- z2 = relu(BN(z1) @ W2^T + b2) + partial BN stats -----------------
__global__ void __launch_bounds__(128) k_z2(const float* __restrict__ b2) {
    __shared__ __align__(16) float2 W2s[(DD/2)*D2];  // 32KB
    __shared__ __align__(16) float X[ESG][DD];       // 8KB
    __shared__ float A1[DD], D1[DD];
    int blk = blockIdx.x, tid = threadIdx.x;
    int c = tid & 63, h = tid >> 6;
    if (tid < DD) { A1[tid] = g_a1[tid]; D1[tid] = g_d1[tid]; }
    {
        const float4* src = (const float4*)g_W2T2;
        float4* dst = (float4*)W2s;
        #pragma unroll
        for (int i = 0; i < 16; ++i)
            cpa16(dst + tid + i*128, src + tid + i*128);
        cpa_commit();
    }
    __syncthreads();
    for (int l = tid; l < ESG*DD; l += 128) {
        int s = l >> 7, kk = l & 127;
        X[s][kk] = g_z1[(blk*ESG + s)*DD + kk] * A1[kk] + D1[kk];
    }
    cpa_wait0();
    __syncthreads();
    ull acc[8];
    #pragma unroll
    for (int i = 0; i < 8; ++i) acc[i] = 0ull;
    #pragma unroll 8
    for (int p = 0; p < DD/2; ++p) {
        ull wv = *(const ull*)&W2s[p*D2 + c];
        #pragma unroll
        for (int i = 0; i < 8; ++i) {
            ull x = *(const ull*)&X[h*8 + i][2*p];
            ffma2(acc[i], wv, x);
        }
    }
    float bb = b2[c];
    float lsum = 0.f, lss = 0.f;
    #pragma unroll
    for (int i = 0; i < 8; ++i) {
        float z = sum2(acc[i]) + bb;
        z = z > 0.f ? z : 0.f;
        g_z2[(blk*ESG + h*8 + i)*D2 + c] = z;
        lsum += z; lss += z*z;
    }
    atomicAdd(&g_s2[c], lsum);
    atomicAdd(&g_q2[c], lss);
}

__global__ void k_m2(const float* __restrict__ g2, const float* __restrict__ be2) {
    int c = threadIdx.x;  // 64
    float m = g_s2[c] * (1.0f/BB);
    float v = g_q2[c] * (1.0f/BB) - m*m;
    float r = rsqrtf(v + 1e-5f);
    float a = g2[c] * r;
    g_a2[c] = a;
    g_d2[c] = be2[c] - m*a;
}

// ---------------- pred = sigmoid(BN(z2) @ Wp^T + bp) -------------------------------
__global__ void k_pred(const float* __restrict__ Wp, const float* __restrict__ bp,
                       float* __restrict__ out_pred) {
    int warp = (blockIdx.x*blockDim.x + threadIdx.x) >> 5;
    int lane = threadIdx.x & 31;
    if (warp >= BB) return;
    float t = 0.f;
    #pragma unroll
    for (int j = 0; j < 2; ++j) {
        int cidx = lane + j*32;
        float f2 = g_z2[warp*D2 + cidx] * g_a2[cidx] + g_d2[cidx];
        t += f2 * Wp[cidx];
    }
    #pragma unroll
    for (int o = 16; o; o >>= 1) t += __shfl_down_sync(0xffffffffu, t, o);
    if (lane == 0) out_pred[warp] = 1.0f / (1.0f + expf(-(t + bp[0])));
}

// ---------------- launch ------------------------------------------------------------
extern "C" void kernel_launch(void* const* d_in, const int* in_sizes, int n_in,
                              void* d_out, int out_size) {
    const int*   nodes_u     = (const int*)  d_in[0];
    const int*   nodes_v     = (const int*)  d_in[1];
    const int*   nodes_d     = (const int*)  d_in[2];
    const int*   inter_items = (const int*)  d_in[3];
    const int*   top_n       = (const int*)  d_in[4];
    const float* protos      = (const float*)d_in[5];
    const float* pre_text    = (const float*)d_in[6];
    const float* pre_visual  = (const float*)d_in[7];
    const float* Wt          = (const float*)d_in[8];
    const float* bt          = (const float*)d_in[9];
    const float* Wv          = (const float*)d_in[10];
    const float* bv          = (const float*)d_in[11];
    const float* up          = (const float*)d_in[12];
    const float* ip          = (const float*)d_in[13];
    const float* dp          = (const float*)d_in[14];
    const float* W1          = (const float*)d_in[15];
    const float* b1          = (const float*)d_in[16];
    const float* g1          = (const float*)d_in[17];
    const float* be1         = (const float*)d_in[18];
    const float* W2          = (const float*)d_in[19];
    const float* b2          = (const float*)d_in[20];
    const float* g2          = (const float*)d_in[21];
    const float* be2         = (const float*)d_in[22];
    const float* Wp          = (const float*)d_in[23];
    const float* bp          = (const float*)d_in[24];

    float* out      = (float*)d_out;
    float* out_pred = out;
    float* out_pu   = out + BB;
    float* out_hu   = out + BB + BB*DD;
    float* out_pd   = out + BB + 2*BB*DD;

    cudaFuncSetAttribute(k_hu_mma, cudaFuncAttributeMaxDynamicSharedMemorySize, HU_SMEM);

    k_prep<<<296, 256>>>(Wt, Wv, W1, W2, protos);
    k_cb<<<DD, 256>>>(Wt, Wv, bt, bv);
    k_mask<<<BB, 128>>>(nodes_u, nodes_d, inter_items, top_n, up, dp, out_pu, out_pd);
    k_e<<<BB/ESB, 256>>>(nodes_v, pre_text, pre_visual, ip);
    k_hu_mma<<<BB/32, 256, HU_SMEM>>>(nodes_d, dp, out_hu);
    k_z1<<<BB/ESB, 256>>>(b1);
    k_m1<<<1, 128>>>(g1, be1);
    k_z2<<<BB/ESG, 128>>>(b2);
    k_m2<<<1, 64>>>(g2, be2);
    k_pred<<<BB/8, 256>>>(Wp, bp, out_pred);
}

// round 8
// speedup vs baseline: 1.3253x; 1.0812x over previous
#include <cuda_runtime.h>
#include <cuda_bf16.h>
#include <cstdint>

// Problem constants
#define BB    4096
#define DD    128
#define HIST  50
#define TOPN  4
#define PROTO 1024
#define ITEMS 100000
#define KTOT  1152      // 384 text + 768 visual
#define K1    256       // MLP layer1 input
#define D2    64        // MLP layer2 output
#define ESB   32        // samples per FFMA2-GEMM block
#define ESG   16        // samples per z2 block
#define CH    32        // K-floats per chunk
#define XPAD  4

typedef unsigned long long ull;

// ---------------- scratch (__device__ globals; no allocation allowed) ----------------
__device__ float2 g_W1T2[(K1/2)*DD];
__device__ float2 g_W2T2[(DD/2)*D2];
__device__ float  g_cb[DD];             // bt·Wt_row + bv·Wv_row
__device__ uint4  g_maskh4[BB*PROTO/8]; // bf16 0/1 presence mask (8MB)
__device__ __align__(16) __nv_bfloat16 g_PB2[2*128*1024];  // bf16 split protos^T [split][c][k]
__device__ __align__(16) __nv_bfloat16 g_WB2[2*128*KTOT];  // bf16 split [Wt|Wv]  [split][c][k]
__device__ __align__(16) __nv_bfloat16 g_XB[2*BB*KTOT];    // bf16 split gathered features
__device__ float  g_cinv[BB];           // 1/unique-count
__device__ float  g_IF[BB*K1];          // inter_feat
__device__ float  g_z1[BB*DD];
__device__ float  g_z2[BB*D2];
__device__ float  g_s1[DD], g_q1[DD], g_a1[DD], g_d1[DD];
__device__ float  g_s2[D2], g_q2[D2], g_a2[D2], g_d2[D2];

__device__ __forceinline__ void ffma2(ull &acc, ull a, ull b) {
    asm("fma.rn.f32x2 %0, %1, %2, %0;" : "+l"(acc) : "l"(a), "l"(b));
}
__device__ __forceinline__ float sum2(ull v) {
    return __uint_as_float((unsigned)v) + __uint_as_float((unsigned)(v >> 32));
}
__device__ __forceinline__ void cpa16(void* dst, const void* src) {
    unsigned d = (unsigned)__cvta_generic_to_shared(dst);
    asm volatile("cp.async.cg.shared.global [%0], [%1], 16;" :: "r"(d), "l"(src));
}
__device__ __forceinline__ void cpa_commit() { asm volatile("cp.async.commit_group;"); }
__device__ __forceinline__ void cpa_wait1() { asm volatile("cp.async.wait_group 1;"); }
__device__ __forceinline__ void cpa_wait0() { asm volatile("cp.async.wait_group 0;"); }

// HMMA bf16: D(f32) += A(bf16 m16k16 row) * B(bf16 k16n8 col)
__device__ __forceinline__ void mma_bf16(float* d, uint32_t a0, uint32_t a1,
                                         uint32_t a2, uint32_t a3,
                                         uint32_t b0, uint32_t b1) {
    asm volatile("mma.sync.aligned.m16n8k16.row.col.f32.bf16.bf16.f32 "
                 "{%0,%1,%2,%3},{%4,%5,%6,%7},{%8,%9},{%0,%1,%2,%3};"
                 : "+f"(d[0]), "+f"(d[1]), "+f"(d[2]), "+f"(d[3])
                 : "r"(a0), "r"(a1), "r"(a2), "r"(a3), "r"(b0), "r"(b1));
}
__device__ __forceinline__ uint32_t pk_bf2(float lo, float hi) {
    uint32_t r;
    asm("cvt.rn.bf16x2.f32 %0, %1, %2;" : "=r"(r) : "f"(hi), "f"(lo));
    return r;
}

// ---------------- prep: weight splits/layouts + zero stats --------------------------
__global__ void k_prep(const float* __restrict__ Wt, const float* __restrict__ Wv,
                       const float* __restrict__ W1, const float* __restrict__ W2,
                       const float* __restrict__ protos) {
    const int n_wb = 128*KTOT;          // 147456 (2 outputs each)
    const int n_pb = 128*1024;          // 131072 (2 outputs each)
    const int n_w1 = (K1/2)*DD;         // 16384
    const int n_w2 = (DD/2)*D2;         // 4096
    const int n_z  = 2*DD + 2*D2;
    int total = n_wb + n_pb + n_w1 + n_w2 + n_z;
    for (int i = blockIdx.x*blockDim.x + threadIdx.x; i < total; i += gridDim.x*blockDim.x) {
        if (i < n_wb) {
            int c = i / KTOT, k = i % KTOT;
            float v = (k < 384) ? Wt[c*384 + k] : Wv[c*768 + (k - 384)];
            __nv_bfloat16 b1 = __float2bfloat16(v);
            g_WB2[i]                = b1;
            g_WB2[128*KTOT + i]     = __float2bfloat16(v - __bfloat162float(b1));
        } else if (i < n_wb + n_pb) {
            int j = i - n_wb; int c = j & 127; int k = j >> 7;
            float p = protos[k*DD + c];
            __nv_bfloat16 b1 = __float2bfloat16(p);
            g_PB2[c*1024 + k]          = b1;
            g_PB2[131072 + c*1024 + k] = __float2bfloat16(p - __bfloat162float(b1));
        } else if (i < n_wb + n_pb + n_w1) {
            int j = i - n_wb - n_pb; int k2 = j / DD, c = j % DD;
            g_W1T2[j] = make_float2(W1[c*K1 + 2*k2], W1[c*K1 + 2*k2 + 1]);
        } else if (i < n_wb + n_pb + n_w1 + n_w2) {
            int j = i - n_wb - n_pb - n_w1; int k2 = j / D2, c = j % D2;
            g_W2T2[j] = make_float2(W2[c*DD + 2*k2], W2[c*DD + 2*k2 + 1]);
        } else {
            int j = i - n_wb - n_pb - n_w1 - n_w2;
            if (j < DD)            g_s1[j] = 0.f;
            else if (j < 2*DD)     g_q1[j-DD] = 0.f;
            else if (j < 2*DD+D2)  g_s2[j-2*DD] = 0.f;
            else                   g_q2[j-2*DD-D2] = 0.f;
        }
    }
}

// cb[c] = bt·Wt[c,:] + bv·Wv[c,:]
__global__ void k_cb(const float* __restrict__ Wt, const float* __restrict__ Wv,
                     const float* __restrict__ bt, const float* __restrict__ bv) {
    int c = blockIdx.x, t = threadIdx.x;
    float s = 0.f;
    for (int k = t; k < 384; k += 256) s += bt[k] * Wt[c*384 + k];
    for (int k = t; k < 768; k += 256) s += bv[k] * Wv[c*768 + k];
    __shared__ float red[256];
    red[t] = s; __syncthreads();
    for (int o = 128; o; o >>= 1) { if (t < o) red[t] += red[t+o]; __syncthreads(); }
    if (t == 0) g_cb[c] = red[0];
}

// ---------------- gather + 2-way bf16 split of features at nodes_v ------------------
__global__ void __launch_bounds__(288) k_xb(const int* __restrict__ nodes_v,
                                            const float* __restrict__ pre_text,
                                            const float* __restrict__ pre_visual) {
    int s = blockIdx.x, t = threadIdx.x;   // 288 threads, 4 elems each
    int row = nodes_v[s];
    float4 v = (t < 96) ? ((const float4*)(pre_text + (size_t)row*384))[t]
                        : ((const float4*)(pre_visual + (size_t)row*768))[t - 96];
    float f[4] = {v.x, v.y, v.z, v.w};
    float r[4];
    __nv_bfloat16 hb[4];
    #pragma unroll
    for (int q = 0; q < 4; ++q) {
        hb[q] = __float2bfloat16(f[q]);
        r[q] = f[q] - __bfloat162float(hb[q]);
    }
    uint32_t h0, h1;
    memcpy(&h0, &hb[0], 4); memcpy(&h1, &hb[2], 4);
    uint32_t l0 = pk_bf2(r[0], r[1]);
    uint32_t l1 = pk_bf2(r[2], r[3]);
    size_t off = (size_t)s*KTOT + 4*t;
    *(uint2*)(g_XB + off)            = make_uint2(h0, h1);
    *(uint2*)(g_XB + (size_t)BB*KTOT + off) = make_uint2(l0, l1);
}

// ---------------- mask build: bitmask -> bf16 mask + counts + prompt gathers --------
__global__ void k_mask(const int* __restrict__ nodes_u, const int* __restrict__ nodes_d,
                       const int* __restrict__ inter_items, const int* __restrict__ top_n,
                       const float* __restrict__ up, const float* __restrict__ dp,
                       float* __restrict__ out_pu, float* __restrict__ out_pd) {
    __shared__ unsigned bm[PROTO/32];
    int i = blockIdx.x, tid = threadIdx.x;
    if (tid < 32) bm[tid] = 0u;
    __syncthreads();
    for (int j = tid; j < HIST*8; j += 128) {
        int h = j >> 3, r = j & 7;
        int item = inter_items[i*HIST + h];
        int p = (r < 4) ? top_n[item*TOPN + r] : top_n[(item + ITEMS)*TOPN + (r - 4)];
        atomicOr(&bm[p >> 5], 1u << (p & 31));
    }
    __syncthreads();
    if (tid < 32) {
        unsigned c = __popc(bm[tid]);
        #pragma unroll
        for (int o = 16; o; o >>= 1) c += __shfl_down_sync(0xffffffffu, c, o);
        if (tid == 0) g_cinv[i] = 1.0f / (float)c;
    }
    unsigned w = bm[tid >> 2];
    int sh = (tid & 3) * 8;
    uint32_t pk[4];
    #pragma unroll
    for (int q = 0; q < 4; ++q) {
        uint32_t lo = ((w >> (sh + 2*q)) & 1) ? 0x3F80u : 0u;
        uint32_t hi = ((w >> (sh + 2*q + 1)) & 1) ? 0x3F80u : 0u;
        pk[q] = lo | (hi << 16);
    }
    g_maskh4[(size_t)i*128 + tid] = make_uint4(pk[0], pk[1], pk[2], pk[3]);
    out_pu[i*DD + tid] = up[nodes_u[i]*DD + tid];
    out_pd[i*DD + tid] = dp[nodes_d[i]*DD + tid];
}

// ===================================================================================
// HMMA GEMM skeleton: 128 CTAs x 256 thr; per CTA M=32 samples, N=128 cols.
// BK=64; smem row stride 72 bf16 (144B) -> conflict-free LDS.32 fragment loads.
// Warp w covers cols [w*16, w*16+16). Frags 2(m16) x 2(n8) x 4 f32.
// ===================================================================================
#define HU_BK   64
#define HU_ST   72
#define HU_ABUF (32*HU_ST*2)        // 4608 B
#define HU_BBUF (128*HU_ST*2)       // 18432 B
#define HU_BUF  (HU_ABUF + HU_BBUF) // 23040 B
#define HU_SMEM (3*HU_BUF)          // 69120 B

#define MMA_FRAG_LOOP(A_, B_)                                                   \
    _Pragma("unroll")                                                           \
    for (int ks = 0; ks < HU_BK/16; ++ks) {                                     \
        int k = ks*16 + kb;                                                     \
        _Pragma("unroll")                                                       \
        for (int mi = 0; mi < 2; ++mi) {                                        \
            int r0 = mi*16 + gr;                                                \
            uint32_t a0 = *(const uint32_t*)&A_[r0*HU_ST + k];                  \
            uint32_t a1 = *(const uint32_t*)&A_[(r0+8)*HU_ST + k];              \
            uint32_t a2 = *(const uint32_t*)&A_[r0*HU_ST + k + 8];              \
            uint32_t a3 = *(const uint32_t*)&A_[(r0+8)*HU_ST + k + 8];          \
            _Pragma("unroll")                                                   \
            for (int ni = 0; ni < 2; ++ni) {                                    \
                int n = w*16 + ni*8 + gr;                                       \
                uint32_t b0 = *(const uint32_t*)&B_[n*HU_ST + k];               \
                uint32_t b1 = *(const uint32_t*)&B_[n*HU_ST + k + 8];           \
                mma_bf16(d[mi][ni], a0, a1, a2, a3, b0, b1);                    \
            }                                                                   \
        }                                                                       \
    }

// ---------------- h_u via mma.sync: D = mask @ (B1 | B2 stacked in K) ---------------
__global__ void __launch_bounds__(256) k_hu_mma(const int* __restrict__ nodes_d,
                                                const float* __restrict__ dp,
                                                float* __restrict__ out_hu) {
    extern __shared__ char sm[];
    int blk = blockIdx.x, tid = threadIdx.x;
    int w = tid >> 5, lane = tid & 31;
    int gr = lane >> 2, kb = (lane & 3) * 2;

    auto stage = [&](int ch, int b) {
        char* Ad = sm + b*HU_BUF;
        char* Bd = Ad + HU_ABUF;
        int k0 = ch * HU_BK;
        int split = k0 >> 10, kk = k0 & 1023;
        const char* asrc = (const char*)g_maskh4
                         + (size_t)(blk*32 + (tid >> 3))*2048 + kk*2 + (tid & 7)*16;
        cpa16(Ad + (tid >> 3)*144 + (tid & 7)*16, asrc);
        const char* bbase = (const char*)g_PB2 + ((size_t)split << 18);
        #pragma unroll
        for (int i = 0; i < 4; ++i) {
            int idx = tid + i*256; int c = idx >> 3, pc = idx & 7;
            cpa16(Bd + c*144 + pc*16, bbase + (size_t)c*2048 + kk*2 + pc*16);
        }
        cpa_commit();
    };

    float d[2][2][4];
    #pragma unroll
    for (int mi = 0; mi < 2; ++mi)
        #pragma unroll
        for (int ni = 0; ni < 2; ++ni)
            #pragma unroll
            for (int q = 0; q < 4; ++q) d[mi][ni][q] = 0.f;

    const int NCH = 2048/HU_BK;   // 32
    stage(0, 0); stage(1, 1);
    #pragma unroll 1
    for (int ch = 0; ch < NCH; ++ch) {
        __syncthreads();
        if (ch + 2 < NCH) stage(ch + 2, (ch + 2) % 3);
        if (ch + 2 < NCH) { asm volatile("cp.async.wait_group 2;"); }
        else if (ch + 1 < NCH) cpa_wait1();
        else cpa_wait0();
        __syncthreads();
        const __nv_bfloat16* A = (const __nv_bfloat16*)(sm + (ch % 3)*HU_BUF);
        const __nv_bfloat16* B = (const __nv_bfloat16*)(sm + (ch % 3)*HU_BUF + HU_ABUF);
        MMA_FRAG_LOOP(A, B);
    }
    #pragma unroll
    for (int mi = 0; mi < 2; ++mi) {
        #pragma unroll
        for (int rr = 0; rr < 2; ++rr) {
            int s = blk*32 + mi*16 + gr + rr*8;
            float inv = g_cinv[s];
            const float* pdr = dp + nodes_d[s]*DD;
            #pragma unroll
            for (int ni = 0; ni < 2; ++ni) {
                int c = w*16 + ni*8 + (lane & 3)*2;
                float h0 = d[mi][ni][rr*2]   * inv;
                float h1 = d[mi][ni][rr*2+1] * inv;
                *(float2*)&out_hu[s*DD + c] = make_float2(h0, h1);
                float2 pd = *(const float2*)&pdr[c];
                *(float2*)&g_IF[s*K1 + c] = make_float2(h0 + pd.x, h1 + pd.y);
            }
        }
    }
}

// ---------------- e_i_hat via mma.sync: x1w1 + x1w2 + x2w1 (K_ext = 3*1152) ---------
__global__ void __launch_bounds__(256) k_e_mma(const int* __restrict__ nodes_v,
                                               const float* __restrict__ ip) {
    extern __shared__ char sm[];
    int blk = blockIdx.x, tid = threadIdx.x;
    int w = tid >> 5, lane = tid & 31;
    int gr = lane >> 2, kb = (lane & 3) * 2;

    auto stage = [&](int ch, int b) {
        char* Ad = sm + b*HU_BUF;
        char* Bd = Ad + HU_ABUF;
        int seg = ch / 18;                 // 0: x1w1, 1: x1w2, 2: x2w1
        int kk = (ch % 18) * HU_BK;        // K offset within 1152
        int sa = (seg == 2) ? 1 : 0;
        int sb = (seg == 1) ? 1 : 0;
        const char* abase = (const char*)g_XB + (size_t)sa*BB*KTOT*2;
        const char* asrc = abase + (size_t)(blk*32 + (tid >> 3))*(KTOT*2) + kk*2 + (tid & 7)*16;
        cpa16(Ad + (tid >> 3)*144 + (tid & 7)*16, asrc);
        const char* bbase = (const char*)g_WB2 + (size_t)sb*128*KTOT*2;
        #pragma unroll
        for (int i = 0; i < 4; ++i) {
            int idx = tid + i*256; int c = idx >> 3, pc = idx & 7;
            cpa16(Bd + c*144 + pc*16, bbase + (size_t)c*(KTOT*2) + kk*2 + pc*16);
        }
        cpa_commit();
    };

    float d[2][2][4];
    #pragma unroll
    for (int mi = 0; mi < 2; ++mi)
        #pragma unroll
        for (int ni = 0; ni < 2; ++ni)
            #pragma unroll
            for (int q = 0; q < 4; ++q) d[mi][ni][q] = 0.f;

    const int NCH = 54;    // 3 segments x 18 chunks
    stage(0, 0); stage(1, 1);
    #pragma unroll 1
    for (int ch = 0; ch < NCH; ++ch) {
        __syncthreads();
        if (ch + 2 < NCH) stage(ch + 2, (ch + 2) % 3);
        if (ch + 2 < NCH) { asm volatile("cp.async.wait_group 2;"); }
        else if (ch + 1 < NCH) cpa_wait1();
        else cpa_wait0();
        __syncthreads();
        const __nv_bfloat16* A = (const __nv_bfloat16*)(sm + (ch % 3)*HU_BUF);
        const __nv_bfloat16* B = (const __nv_bfloat16*)(sm + (ch % 3)*HU_BUF + HU_ABUF);
        MMA_FRAG_LOOP(A, B);
    }
    #pragma unroll
    for (int mi = 0; mi < 2; ++mi) {
        #pragma unroll
        for (int rr = 0; rr < 2; ++rr) {
            int s = blk*32 + mi*16 + gr + rr*8;
            int iv = nodes_v[s];
            #pragma unroll
            for (int ni = 0; ni < 2; ++ni) {
                int c = w*16 + ni*8 + (lane & 3)*2;
                float2 cbv = *(const float2*)&g_cb[c];
                float2 ipv = *(const float2*)&ip[(size_t)iv*DD + c];
                float e0 = d[mi][ni][rr*2]   - cbv.x + ipv.x;
                float e1 = d[mi][ni][rr*2+1] - cbv.y + ipv.y;
                *(float2*)&g_IF[s*K1 + DD + c] = make_float2(e0, e1);
            }
        }
    }
}

// ===================================================================================
// FFMA2 GEMM tile (256 threads, 32 samples, grid=128, 3-stage pipeline) for z1
// ===================================================================================
#define GEMM_CORE(Wb_, Xb_, bsel)                                              \
    _Pragma("unroll")                                                          \
    for (int p2 = 0; p2 < 8; ++p2) {                                           \
        ulonglong2 w0 = Wb_[bsel][(2*p2)*64 + cg];                             \
        ulonglong2 w1 = Wb_[bsel][(2*p2+1)*64 + cg];                           \
        _Pragma("unroll")                                                      \
        for (int i = 0; i < 8; ++i) {                                          \
            ulonglong2 x = *(const ulonglong2*)&Xb_[bsel][i*4 + sg][4*p2];     \
            ffma2(acc[i][0], w0.x, x.x);                                       \
            ffma2(acc[i][1], w0.y, x.x);                                       \
            ffma2(acc[i][0], w1.x, x.y);                                       \
            ffma2(acc[i][1], w1.y, x.y);                                       \
        }                                                                      \
    }

#define PIPE_WAIT(ch_, nch_)                                                   \
    if ((ch_) + 2 < (nch_)) { asm volatile("cp.async.wait_group 2;"); }        \
    else if ((ch_) + 1 < (nch_)) cpa_wait1();                                  \
    else cpa_wait0();

// ---------------- z1 = relu(IF @ W1^T + b1) + partial BN stats ---------------------
__global__ void __launch_bounds__(256) k_z1(const float* __restrict__ b1) {
    __shared__ __align__(16) ulonglong2 Wb[3][16*64];
    __shared__ __align__(16) float Xb[3][ESB][CH+XPAD];
    int blk = blockIdx.x, tid = threadIdx.x;
    int w = tid >> 5, lane = tid & 31;
    int sg = lane >> 3, cgl = lane & 7, cg = w*8 + cgl;
    int c0 = cg*2;
    int xs = tid >> 3, xj = tid & 7;

    auto stage = [&](int ch, int b) {
        const float4* wsrc = (const float4*)(g_W1T2 + (ch*(CH/2))*DD);
        const float4* wdst = (const float4*)Wb[b];
        #pragma unroll
        for (int i = 0; i < 4; ++i)
            cpa16((void*)(wdst + tid*4 + i), wsrc + tid*4 + i);
        cpa16(&Xb[b][xs][xj*4], &g_IF[(blk*ESB + xs)*K1 + ch*CH + xj*4]);
        cpa_commit();
    };

    ull acc[8][2];
    #pragma unroll
    for (int i = 0; i < 8; ++i) { acc[i][0] = 0ull; acc[i][1] = 0ull; }

    const int NCH = K1/CH;  // 8
    stage(0, 0); stage(1, 1);
    #pragma unroll 1
    for (int ch = 0; ch < NCH; ++ch) {
        __syncthreads();
        if (ch + 2 < NCH) stage(ch + 2, (ch + 2) % 3);
        PIPE_WAIT(ch, NCH);
        __syncthreads();
        GEMM_CORE(Wb, Xb, ch % 3);
    }
    float2 bb = *(const float2*)&b1[c0];
    float s0 = 0.f, s1 = 0.f, q0 = 0.f, q1 = 0.f;
    #pragma unroll
    for (int i = 0; i < 8; ++i) {
        int s = blk*ESB + i*4 + sg;
        float z0 = sum2(acc[i][0]) + bb.x;  z0 = z0 > 0.f ? z0 : 0.f;
        float z1v = sum2(acc[i][1]) + bb.y; z1v = z1v > 0.f ? z1v : 0.f;
        *(float2*)&g_z1[s*DD + c0] = make_float2(z0, z1v);
        s0 += z0; s1 += z1v; q0 += z0*z0; q1 += z1v*z1v;
    }
    #pragma unroll
    for (int o = 8; o <= 16; o <<= 1) {
        s0 += __shfl_xor_sync(0xffffffffu, s0, o);
        s1 += __shfl_xor_sync(0xffffffffu, s1, o);
        q0 += __shfl_xor_sync(0xffffffffu, q0, o);
        q1 += __shfl_xor_sync(0xffffffffu, q1, o);
    }
    if (sg == 0) {
        atomicAdd(&g_s1[c0], s0);   atomicAdd(&g_s1[c0+1], s1);
        atomicAdd(&g_q1[c0], q0);   atomicAdd(&g_q1[c0+1], q1);
    }
}

__global__ void k_m1(const float* __restrict__ g1, const float* __restrict__ be1) {
    int c = threadIdx.x;  // 128
    float m = g_s1[c] * (1.0f/BB);
    float v = g_q1[c] * (1.0f/BB) - m*m;
    float r = rsqrtf(v + 1e-5f);
    float a = g1[c] * r;
    g_a1[c] = a;
    g_d1[c] = be1[c] - m*a;
}

// ---------------- z2 = relu(BN(z1) @ W2^T + b2) + partial BN stats -----------------
__global__ void __launch_bounds__(128) k_z2(const float* __restrict__ b2) {
    __shared__ __align__(16) float2 W2s[(DD/2)*D2];  // 32KB
    __shared__ __align__(16) float X[ESG][DD];       // 8KB
    __shared__ float A1[DD], D1[DD];
    int blk = blockIdx.x, tid = threadIdx.x;
    int c = tid & 63, h = tid >> 6;
    if (tid < DD) { A1[tid] = g_a1[tid]; D1[tid] = g_d1[tid]; }
    {
        const float4* src = (const float4*)g_W2T2;
        float4* dst = (float4*)W2s;
        #pragma unroll
        for (int i = 0; i < 16; ++i)
            cpa16(dst + tid + i*128, src + tid + i*128);
        cpa_commit();
    }
    __syncthreads();
    for (int l = tid; l < ESG*DD; l += 128) {
        int s = l >> 7, kk = l & 127;
        X[s][kk] = g_z1[(blk*ESG + s)*DD + kk] * A1[kk] + D1[kk];
    }
    cpa_wait0();
    __syncthreads();
    ull acc[8];
    #pragma unroll
    for (int i = 0; i < 8; ++i) acc[i] = 0ull;
    #pragma unroll 8
    for (int p = 0; p < DD/2; ++p) {
        ull wv = *(const ull*)&W2s[p*D2 + c];
        #pragma unroll
        for (int i = 0; i < 8; ++i) {
            ull x = *(const ull*)&X[h*8 + i][2*p];
            ffma2(acc[i], wv, x);
        }
    }
    float bb = b2[c];
    float lsum = 0.f, lss = 0.f;
    #pragma unroll
    for (int i = 0; i < 8; ++i) {
        float z = sum2(acc[i]) + bb;
        z = z > 0.f ? z : 0.f;
        g_z2[(blk*ESG + h*8 + i)*D2 + c] = z;
        lsum += z; lss += z*z;
    }
    atomicAdd(&g_s2[c], lsum);
    atomicAdd(&g_q2[c], lss);
}

__global__ void k_m2(const float* __restrict__ g2, const float* __restrict__ be2) {
    int c = threadIdx.x;  // 64
    float m = g_s2[c] * (1.0f/BB);
    float v = g_q2[c] * (1.0f/BB) - m*m;
    float r = rsqrtf(v + 1e-5f);
    float a = g2[c] * r;
    g_a2[c] = a;
    g_d2[c] = be2[c] - m*a;
}

// ---------------- pred = sigmoid(BN(z2) @ Wp^T + bp) -------------------------------
__global__ void k_pred(const float* __restrict__ Wp, const float* __restrict__ bp,
                       float* __restrict__ out_pred) {
    int warp = (blockIdx.x*blockDim.x + threadIdx.x) >> 5;
    int lane = threadIdx.x & 31;
    if (warp >= BB) return;
    float t = 0.f;
    #pragma unroll
    for (int j = 0; j < 2; ++j) {
        int cidx = lane + j*32;
        float f2 = g_z2[warp*D2 + cidx] * g_a2[cidx] + g_d2[cidx];
        t += f2 * Wp[cidx];
    }
    #pragma unroll
    for (int o = 16; o; o >>= 1) t += __shfl_down_sync(0xffffffffu, t, o);
    if (lane == 0) out_pred[warp] = 1.0f / (1.0f + expf(-(t + bp[0])));
}

// ---------------- launch ------------------------------------------------------------
extern "C" void kernel_launch(void* const* d_in, const int* in_sizes, int n_in,
                              void* d_out, int out_size) {
    const int*   nodes_u     = (const int*)  d_in[0];
    const int*   nodes_v     = (const int*)  d_in[1];
    const int*   nodes_d     = (const int*)  d_in[2];
    const int*   inter_items = (const int*)  d_in[3];
    const int*   top_n       = (const int*)  d_in[4];
    const float* protos      = (const float*)d_in[5];
    const float* pre_text    = (const float*)d_in[6];
    const float* pre_visual  = (const float*)d_in[7];
    const float* Wt          = (const float*)d_in[8];
    const float* bt          = (const float*)d_in[9];
    const float* Wv          = (const float*)d_in[10];
    const float* bv          = (const float*)d_in[11];
    const float* up          = (const float*)d_in[12];
    const float* ip          = (const float*)d_in[13];
    const float* dp          = (const float*)d_in[14];
    const float* W1          = (const float*)d_in[15];
    const float* b1          = (const float*)d_in[16];
    const float* g1          = (const float*)d_in[17];
    const float* be1         = (const float*)d_in[18];
    const float* W2          = (const float*)d_in[19];
    const float* b2          = (const float*)d_in[20];
    const float* g2          = (const float*)d_in[21];
    const float* be2         = (const float*)d_in[22];
    const float* Wp          = (const float*)d_in[23];
    const float* bp          = (const float*)d_in[24];

    float* out      = (float*)d_out;
    float* out_pred = out;
    float* out_pu   = out + BB;
    float* out_hu   = out + BB + BB*DD;
    float* out_pd   = out + BB + 2*BB*DD;

    cudaFuncSetAttribute(k_hu_mma, cudaFuncAttributeMaxDynamicSharedMemorySize, HU_SMEM);
    cudaFuncSetAttribute(k_e_mma,  cudaFuncAttributeMaxDynamicSharedMemorySize, HU_SMEM);

    k_prep<<<296, 256>>>(Wt, Wv, W1, W2, protos);
    k_cb<<<DD, 256>>>(Wt, Wv, bt, bv);
    k_xb<<<BB, 288>>>(nodes_v, pre_text, pre_visual);
    k_mask<<<BB, 128>>>(nodes_u, nodes_d, inter_items, top_n, up, dp, out_pu, out_pd);
    k_e_mma<<<BB/32, 256, HU_SMEM>>>(nodes_v, ip);
    k_hu_mma<<<BB/32, 256, HU_SMEM>>>(nodes_d, dp, out_hu);
    k_z1<<<BB/ESB, 256>>>(b1);
    k_m1<<<1, 128>>>(g1, be1);
    k_z2<<<BB/ESG, 128>>>(b2);
    k_m2<<<1, 64>>>(g2, be2);
    k_pred<<<BB/8, 256>>>(Wp, bp, out_pred);
}

// round 9
// speedup vs baseline: 1.5518x; 1.1709x over previous
#include <cuda_runtime.h>
#include <cuda_bf16.h>
#include <cstdint>

// Problem constants
#define BB    4096
#define DD    128
#define HIST  50
#define TOPN  4
#define PROTO 1024
#define ITEMS 100000
#define KTOT  1152      // 384 text + 768 visual
#define K1    256       // MLP layer1 input
#define D2    64        // MLP layer2 output
#define ESG   16        // samples per z2 block

typedef unsigned long long ull;

// ---------------- scratch (__device__ globals; no allocation allowed) ----------------
__device__ float2 g_W2T2[(DD/2)*D2];
__device__ float  g_cb[DD];             // bt·Wt_row + bv·Wv_row
__device__ uint4  g_maskh4[BB*PROTO/8]; // bf16 0/1 presence mask (8MB)
__device__ __align__(16) __nv_bfloat16 g_PB2[2*128*1024];  // bf16 split protos^T [split][c][k]
__device__ __align__(16) __nv_bfloat16 g_WB2[2*128*KTOT];  // bf16 split [Wt|Wv]  [split][c][k]
__device__ __align__(16) __nv_bfloat16 g_W1B2[2*128*K1];   // bf16 split W1       [split][c][k]
__device__ __align__(16) __nv_bfloat16 g_XB[2*BB*KTOT];    // bf16 split gathered features
__device__ __align__(16) __nv_bfloat16 g_IFB[2*BB*K1];     // bf16 split inter_feat
__device__ float  g_cinv[BB];           // 1/unique-count
__device__ float  g_z1[BB*DD];
__device__ float  g_z2[BB*D2];
__device__ float  g_s1[DD], g_q1[DD], g_a1[DD], g_d1[DD];
__device__ float  g_s2[D2], g_q2[D2], g_a2[D2], g_d2[D2];

__device__ __forceinline__ void ffma2(ull &acc, ull a, ull b) {
    asm("fma.rn.f32x2 %0, %1, %2, %0;" : "+l"(acc) : "l"(a), "l"(b));
}
__device__ __forceinline__ float sum2(ull v) {
    return __uint_as_float((unsigned)v) + __uint_as_float((unsigned)(v >> 32));
}
__device__ __forceinline__ void cpa16(void* dst, const void* src) {
    unsigned d = (unsigned)__cvta_generic_to_shared(dst);
    asm volatile("cp.async.cg.shared.global [%0], [%1], 16;" :: "r"(d), "l"(src));
}
__device__ __forceinline__ void cpa_commit() { asm volatile("cp.async.commit_group;"); }
__device__ __forceinline__ void cpa_wait1() { asm volatile("cp.async.wait_group 1;"); }
__device__ __forceinline__ void cpa_wait0() { asm volatile("cp.async.wait_group 0;"); }

// HMMA bf16: D(f32) += A(bf16 m16k16 row) * B(bf16 k16n8 col)
__device__ __forceinline__ void mma_bf16(float* d, uint32_t a0, uint32_t a1,
                                         uint32_t a2, uint32_t a3,
                                         uint32_t b0, uint32_t b1) {
    asm volatile("mma.sync.aligned.m16n8k16.row.col.f32.bf16.bf16.f32 "
                 "{%0,%1,%2,%3},{%4,%5,%6,%7},{%8,%9},{%0,%1,%2,%3};"
                 : "+f"(d[0]), "+f"(d[1]), "+f"(d[2]), "+f"(d[3])
                 : "r"(a0), "r"(a1), "r"(a2), "r"(a3), "r"(b0), "r"(b1));
}
__device__ __forceinline__ uint32_t pk_bf2(float lo, float hi) {
    uint32_t r;
    asm("cvt.rn.bf16x2.f32 %0, %1, %2;" : "=r"(r) : "f"(hi), "f"(lo));
    return r;
}
// split pair (v0,v1) -> hi packed, lo packed
__device__ __forceinline__ void split2(float v0, float v1, uint32_t &hi, uint32_t &lo) {
    __nv_bfloat16 h0 = __float2bfloat16(v0), h1 = __float2bfloat16(v1);
    uint16_t u0, u1; memcpy(&u0, &h0, 2); memcpy(&u1, &h1, 2);
    hi = (uint32_t)u0 | ((uint32_t)u1 << 16);
    lo = pk_bf2(v0 - __bfloat162float(h0), v1 - __bfloat162float(h1));
}

// ---------------- prep: weight splits/layouts + zero stats + cb ---------------------
__global__ void k_prep(const float* __restrict__ Wt, const float* __restrict__ Wv,
                       const float* __restrict__ W1, const float* __restrict__ W2,
                       const float* __restrict__ protos,
                       const float* __restrict__ bt, const float* __restrict__ bv) {
    int tid = threadIdx.x;
    if (blockIdx.x >= 296) {   // cb part: 16 blocks x 8 warps = 128 columns
        int c = (blockIdx.x - 296)*8 + (tid >> 5);
        int l = tid & 31;
        float s = 0.f;
        for (int k = l; k < 384; k += 32) s += bt[k] * Wt[c*384 + k];
        for (int k = l; k < 768; k += 32) s += bv[k] * Wv[c*768 + k];
        #pragma unroll
        for (int o = 16; o; o >>= 1) s += __shfl_down_sync(0xffffffffu, s, o);
        if (l == 0) g_cb[c] = s;
        return;
    }
    const int n_wb = 128*KTOT;          // 147456
    const int n_pb = 128*1024;          // 131072
    const int n_w1 = 128*K1;            // 32768
    const int n_w2 = (DD/2)*D2;         // 4096
    const int n_z  = 2*DD + 2*D2;
    int total = n_wb + n_pb + n_w1 + n_w2 + n_z;
    for (int i = blockIdx.x*blockDim.x + tid; i < total; i += 296*blockDim.x) {
        if (i < n_wb) {
            int c = i / KTOT, k = i % KTOT;
            float v = (k < 384) ? Wt[c*384 + k] : Wv[c*768 + (k - 384)];
            __nv_bfloat16 b1 = __float2bfloat16(v);
            g_WB2[i]            = b1;
            g_WB2[128*KTOT + i] = __float2bfloat16(v - __bfloat162float(b1));
        } else if (i < n_wb + n_pb) {
            int j = i - n_wb; int c = j & 127; int k = j >> 7;
            float p = protos[k*DD + c];
            __nv_bfloat16 b1 = __float2bfloat16(p);
            g_PB2[c*1024 + k]          = b1;
            g_PB2[131072 + c*1024 + k] = __float2bfloat16(p - __bfloat162float(b1));
        } else if (i < n_wb + n_pb + n_w1) {
            int j = i - n_wb - n_pb;           // c*K1 + k layout directly
            float v = W1[j];
            __nv_bfloat16 b1 = __float2bfloat16(v);
            g_W1B2[j]            = b1;
            g_W1B2[128*K1 + j]   = __float2bfloat16(v - __bfloat162float(b1));
        } else if (i < n_wb + n_pb + n_w1 + n_w2) {
            int j = i - n_wb - n_pb - n_w1; int k2 = j / D2, c = j % D2;
            g_W2T2[j] = make_float2(W2[c*DD + 2*k2], W2[c*DD + 2*k2 + 1]);
        } else {
            int j = i - n_wb - n_pb - n_w1 - n_w2;
            if (j < DD)            g_s1[j] = 0.f;
            else if (j < 2*DD)     g_q1[j-DD] = 0.f;
            else if (j < 2*DD+D2)  g_s2[j-2*DD] = 0.f;
            else                   g_q2[j-2*DD-D2] = 0.f;
        }
    }
}

// ---------------- gather + 2-way bf16 split of features at nodes_v ------------------
__global__ void __launch_bounds__(288) k_xb(const int* __restrict__ nodes_v,
                                            const float* __restrict__ pre_text,
                                            const float* __restrict__ pre_visual) {
    int s = blockIdx.x, t = threadIdx.x;   // 288 threads, 4 elems each
    int row = nodes_v[s];
    float4 v = (t < 96) ? ((const float4*)(pre_text + (size_t)row*384))[t]
                        : ((const float4*)(pre_visual + (size_t)row*768))[t - 96];
    uint32_t h0, l0, h1, l1;
    split2(v.x, v.y, h0, l0);
    split2(v.z, v.w, h1, l1);
    size_t off = (size_t)s*KTOT + 4*t;
    *(uint2*)(g_XB + off)                   = make_uint2(h0, h1);
    *(uint2*)(g_XB + (size_t)BB*KTOT + off) = make_uint2(l0, l1);
}

// ---------------- mask build: vectorized top_n gather -------------------------------
__global__ void k_mask(const int* __restrict__ nodes_u, const int* __restrict__ nodes_d,
                       const int* __restrict__ inter_items, const int* __restrict__ top_n,
                       const float* __restrict__ up, const float* __restrict__ dp,
                       float* __restrict__ out_pu, float* __restrict__ out_pd) {
    __shared__ unsigned bm[PROTO/32];
    int i = blockIdx.x, tid = threadIdx.x;
    if (tid < 32) bm[tid] = 0u;
    __syncthreads();
    if (tid < HIST) {
        int item = inter_items[i*HIST + tid];
        int4 r1 = ((const int4*)top_n)[item];
        int4 r2 = ((const int4*)top_n)[item + ITEMS];
        atomicOr(&bm[r1.x >> 5], 1u << (r1.x & 31));
        atomicOr(&bm[r1.y >> 5], 1u << (r1.y & 31));
        atomicOr(&bm[r1.z >> 5], 1u << (r1.z & 31));
        atomicOr(&bm[r1.w >> 5], 1u << (r1.w & 31));
        atomicOr(&bm[r2.x >> 5], 1u << (r2.x & 31));
        atomicOr(&bm[r2.y >> 5], 1u << (r2.y & 31));
        atomicOr(&bm[r2.z >> 5], 1u << (r2.z & 31));
        atomicOr(&bm[r2.w >> 5], 1u << (r2.w & 31));
    }
    __syncthreads();
    if (tid < 32) {
        unsigned c = __popc(bm[tid]);
        #pragma unroll
        for (int o = 16; o; o >>= 1) c += __shfl_down_sync(0xffffffffu, c, o);
        if (tid == 0) g_cinv[i] = 1.0f / (float)c;
    }
    unsigned w = bm[tid >> 2];
    int sh = (tid & 3) * 8;
    uint32_t pk[4];
    #pragma unroll
    for (int q = 0; q < 4; ++q) {
        uint32_t lo = ((w >> (sh + 2*q)) & 1) ? 0x3F80u : 0u;
        uint32_t hi = ((w >> (sh + 2*q + 1)) & 1) ? 0x3F80u : 0u;
        pk[q] = lo | (hi << 16);
    }
    g_maskh4[(size_t)i*128 + tid] = make_uint4(pk[0], pk[1], pk[2], pk[3]);
    out_pu[i*DD + tid] = up[nodes_u[i]*DD + tid];
    out_pd[i*DD + tid] = dp[nodes_d[i]*DD + tid];
}

// ===================================================================================
// HMMA GEMM skeleton: 256 thr; per CTA M=32 samples, N=128 cols, BK=64.
// smem row stride 72 bf16 (144B). Warp w covers cols [w*16, w*16+16).
// ===================================================================================
#define HU_BK   64
#define HU_ST   72
#define HU_ABUF (32*HU_ST*2)
#define HU_BBUF (128*HU_ST*2)
#define HU_BUF  (HU_ABUF + HU_BBUF)
#define HU_SMEM (3*HU_BUF)          // 69120 B

#define MMA_FRAG_LOOP(A_, B_)                                                   \
    _Pragma("unroll")                                                           \
    for (int ks = 0; ks < HU_BK/16; ++ks) {                                     \
        int k = ks*16 + kb;                                                     \
        _Pragma("unroll")                                                       \
        for (int mi = 0; mi < 2; ++mi) {                                        \
            int r0 = mi*16 + gr;                                                \
            uint32_t a0 = *(const uint32_t*)&A_[r0*HU_ST + k];                  \
            uint32_t a1 = *(const uint32_t*)&A_[(r0+8)*HU_ST + k];              \
            uint32_t a2 = *(const uint32_t*)&A_[r0*HU_ST + k + 8];              \
            uint32_t a3 = *(const uint32_t*)&A_[(r0+8)*HU_ST + k + 8];          \
            _Pragma("unroll")                                                   \
            for (int ni = 0; ni < 2; ++ni) {                                    \
                int n = w*16 + ni*8 + gr;                                       \
                uint32_t b0 = *(const uint32_t*)&B_[n*HU_ST + k];               \
                uint32_t b1 = *(const uint32_t*)&B_[n*HU_ST + k + 8];           \
                mma_bf16(d[mi][ni], a0, a1, a2, a3, b0, b1);                    \
            }                                                                   \
        }                                                                       \
    }

#define MMA_PIPE(NCH_)                                                          \
    stage(0, 0); stage(1, 1);                                                   \
    _Pragma("unroll 1")                                                         \
    for (int ch = 0; ch < (NCH_); ++ch) {                                       \
        __syncthreads();                                                        \
        if (ch + 2 < (NCH_)) stage(ch + 2, (ch + 2) % 3);                       \
        if (ch + 2 < (NCH_)) { asm volatile("cp.async.wait_group 2;"); }        \
        else if (ch + 1 < (NCH_)) cpa_wait1();                                  \
        else cpa_wait0();                                                       \
        __syncthreads();                                                        \
        const __nv_bfloat16* A = (const __nv_bfloat16*)(sm + (ch % 3)*HU_BUF);  \
        const __nv_bfloat16* B = (const __nv_bfloat16*)(sm + (ch % 3)*HU_BUF + HU_ABUF); \
        MMA_FRAG_LOOP(A, B);                                                    \
    }

#define MMA_DECL                                                                \
    int tid = threadIdx.x;                                                      \
    int w = tid >> 5, lane = tid & 31;                                          \
    int gr = lane >> 2, kb = (lane & 3) * 2;                                    \
    float d[2][2][4];                                                           \
    _Pragma("unroll")                                                           \
    for (int mi = 0; mi < 2; ++mi)                                              \
        _Pragma("unroll")                                                       \
        for (int ni = 0; ni < 2; ++ni)                                          \
            _Pragma("unroll")                                                   \
            for (int q = 0; q < 4; ++q) d[mi][ni][q] = 0.f;

// ---------------- h_u body: D = mask @ (P1 | P2 stacked in K) -----------------------
__device__ __forceinline__ void hu_body(char* sm, int blk,
                                        const int* __restrict__ nodes_d,
                                        const float* __restrict__ dp,
                                        float* __restrict__ out_hu) {
    MMA_DECL;
    auto stage = [&](int ch, int b) {
        char* Ad = sm + b*HU_BUF;
        char* Bd = Ad + HU_ABUF;
        int k0 = ch * HU_BK;
        int split = k0 >> 10, kk = k0 & 1023;
        const char* asrc = (const char*)g_maskh4
                         + (size_t)(blk*32 + (tid >> 3))*2048 + kk*2 + (tid & 7)*16;
        cpa16(Ad + (tid >> 3)*144 + (tid & 7)*16, asrc);
        const char* bbase = (const char*)g_PB2 + ((size_t)split << 18);
        #pragma unroll
        for (int i = 0; i < 4; ++i) {
            int idx = tid + i*256; int c = idx >> 3, pc = idx & 7;
            cpa16(Bd + c*144 + pc*16, bbase + (size_t)c*2048 + kk*2 + pc*16);
        }
        cpa_commit();
    };
    MMA_PIPE(32);
    #pragma unroll
    for (int mi = 0; mi < 2; ++mi) {
        #pragma unroll
        for (int rr = 0; rr < 2; ++rr) {
            int s = blk*32 + mi*16 + gr + rr*8;
            float inv = g_cinv[s];
            const float* pdr = dp + nodes_d[s]*DD;
            #pragma unroll
            for (int ni = 0; ni < 2; ++ni) {
                int c = w*16 + ni*8 + (lane & 3)*2;
                float h0 = d[mi][ni][rr*2]   * inv;
                float h1 = d[mi][ni][rr*2+1] * inv;
                *(float2*)&out_hu[s*DD + c] = make_float2(h0, h1);
                float2 pd = *(const float2*)&pdr[c];
                uint32_t hi, lo;
                split2(h0 + pd.x, h1 + pd.y, hi, lo);
                *(uint32_t*)&g_IFB[(size_t)s*K1 + c]            = hi;
                *(uint32_t*)&g_IFB[(size_t)(BB + s)*K1 + c]     = lo;
            }
        }
    }
}

// ---------------- e body: x1w1 + x1w2 + x2w1 (K_ext = 3*1152) -----------------------
__device__ __forceinline__ void e_body(char* sm, int blk,
                                       const int* __restrict__ nodes_v,
                                       const float* __restrict__ ip) {
    MMA_DECL;
    auto stage = [&](int ch, int b) {
        char* Ad = sm + b*HU_BUF;
        char* Bd = Ad + HU_ABUF;
        int seg = ch / 18;
        int kk = (ch % 18) * HU_BK;
        int sa = (seg == 2) ? 1 : 0;
        int sb = (seg == 1) ? 1 : 0;
        const char* abase = (const char*)g_XB + (size_t)sa*BB*KTOT*2;
        const char* asrc = abase + (size_t)(blk*32 + (tid >> 3))*(KTOT*2) + kk*2 + (tid & 7)*16;
        cpa16(Ad + (tid >> 3)*144 + (tid & 7)*16, asrc);
        const char* bbase = (const char*)g_WB2 + (size_t)sb*128*KTOT*2;
        #pragma unroll
        for (int i = 0; i < 4; ++i) {
            int idx = tid + i*256; int c = idx >> 3, pc = idx & 7;
            cpa16(Bd + c*144 + pc*16, bbase + (size_t)c*(KTOT*2) + kk*2 + pc*16);
        }
        cpa_commit();
    };
    MMA_PIPE(54);
    #pragma unroll
    for (int mi = 0; mi < 2; ++mi) {
        #pragma unroll
        for (int rr = 0; rr < 2; ++rr) {
            int s = blk*32 + mi*16 + gr + rr*8;
            int iv = nodes_v[s];
            #pragma unroll
            for (int ni = 0; ni < 2; ++ni) {
                int c = w*16 + ni*8 + (lane & 3)*2;
                float2 cbv = *(const float2*)&g_cb[c];
                float2 ipv = *(const float2*)&ip[(size_t)iv*DD + c];
                float e0 = d[mi][ni][rr*2]   - cbv.x + ipv.x;
                float e1 = d[mi][ni][rr*2+1] - cbv.y + ipv.y;
                uint32_t hi, lo;
                split2(e0, e1, hi, lo);
                *(uint32_t*)&g_IFB[(size_t)s*K1 + DD + c]        = hi;
                *(uint32_t*)&g_IFB[(size_t)(BB + s)*K1 + DD + c] = lo;
            }
        }
    }
}

// fused: blocks [0,128) do e, [128,256) do hu
__global__ void __launch_bounds__(256) k_eh(const int* __restrict__ nodes_v,
                                            const float* __restrict__ ip,
                                            const int* __restrict__ nodes_d,
                                            const float* __restrict__ dp,
                                            float* __restrict__ out_hu) {
    extern __shared__ char sm[];
    if (blockIdx.x < 128) e_body(sm, blockIdx.x, nodes_v, ip);
    else                  hu_body(sm, blockIdx.x - 128, nodes_d, dp, out_hu);
}

// ---------------- z1 via mma.sync: relu(IF @ W1^T + b1) + BN stats ------------------
__global__ void __launch_bounds__(256) k_z1m(const float* __restrict__ b1) {
    extern __shared__ char sm[];
    int blk = blockIdx.x;
    MMA_DECL;
    auto stage = [&](int ch, int b) {
        char* Ad = sm + b*HU_BUF;
        char* Bd = Ad + HU_ABUF;
        int seg = ch / 4;                  // 12 chunks: 3 segments x 4
        int kk = (ch % 4) * HU_BK;
        int sa = (seg == 2) ? 1 : 0;
        int sb = (seg == 1) ? 1 : 0;
        const char* abase = (const char*)g_IFB + (size_t)sa*BB*K1*2;
        const char* asrc = abase + (size_t)(blk*32 + (tid >> 3))*(K1*2) + kk*2 + (tid & 7)*16;
        cpa16(Ad + (tid >> 3)*144 + (tid & 7)*16, asrc);
        const char* bbase = (const char*)g_W1B2 + (size_t)sb*128*K1*2;
        #pragma unroll
        for (int i = 0; i < 4; ++i) {
            int idx = tid + i*256; int c = idx >> 3, pc = idx & 7;
            cpa16(Bd + c*144 + pc*16, bbase + (size_t)c*(K1*2) + kk*2 + pc*16);
        }
        cpa_commit();
    };
    MMA_PIPE(12);
    float2 bb[2];
    bb[0] = *(const float2*)&b1[w*16 + (lane & 3)*2];
    bb[1] = *(const float2*)&b1[w*16 + 8 + (lane & 3)*2];
    float ps[2][2] = {{0,0},{0,0}}, pq[2][2] = {{0,0},{0,0}};
    #pragma unroll
    for (int mi = 0; mi < 2; ++mi) {
        #pragma unroll
        for (int rr = 0; rr < 2; ++rr) {
            int s = blk*32 + mi*16 + gr + rr*8;
            #pragma unroll
            for (int ni = 0; ni < 2; ++ni) {
                int c = w*16 + ni*8 + (lane & 3)*2;
                float z0 = d[mi][ni][rr*2]   + bb[ni].x; z0 = z0 > 0.f ? z0 : 0.f;
                float z1v = d[mi][ni][rr*2+1] + bb[ni].y; z1v = z1v > 0.f ? z1v : 0.f;
                *(float2*)&g_z1[s*DD + c] = make_float2(z0, z1v);
                ps[ni][0] += z0; ps[ni][1] += z1v;
                pq[ni][0] += z0*z0; pq[ni][1] += z1v*z1v;
            }
        }
    }
    #pragma unroll
    for (int ni = 0; ni < 2; ++ni) {
        #pragma unroll
        for (int q = 0; q < 2; ++q) {
            #pragma unroll
            for (int o = 4; o <= 16; o <<= 1) {
                ps[ni][q] += __shfl_xor_sync(0xffffffffu, ps[ni][q], o);
                pq[ni][q] += __shfl_xor_sync(0xffffffffu, pq[ni][q], o);
            }
        }
        if (lane < 4) {
            int c = w*16 + ni*8 + lane*2;
            atomicAdd(&g_s1[c],   ps[ni][0]); atomicAdd(&g_s1[c+1], ps[ni][1]);
            atomicAdd(&g_q1[c],   pq[ni][0]); atomicAdd(&g_q1[c+1], pq[ni][1]);
        }
    }
}

__global__ void k_m1(const float* __restrict__ g1, const float* __restrict__ be1) {
    int c = threadIdx.x;  // 128
    float m = g_s1[c] * (1.0f/BB);
    float v = g_q1[c] * (1.0f/BB) - m*m;
    float r = rsqrtf(v + 1e-5f);
    float a = g1[c] * r;
    g_a1[c] = a;
    g_d1[c] = be1[c] - m*a;
}

// ---------------- z2 = relu(BN(z1) @ W2^T + b2) + partial BN stats -----------------
__global__ void __launch_bounds__(128) k_z2(const float* __restrict__ b2) {
    __shared__ __align__(16) float2 W2s[(DD/2)*D2];  // 32KB
    __shared__ __align__(16) float X[ESG][DD];       // 8KB
    __shared__ float A1[DD], D1[DD];
    int blk = blockIdx.x, tid = threadIdx.x;
    int c = tid & 63, h = tid >> 6;
    if (tid < DD) { A1[tid] = g_a1[tid]; D1[tid] = g_d1[tid]; }
    {
        const float4* src = (const float4*)g_W2T2;
        float4* dst = (float4*)W2s;
        #pragma unroll
        for (int i = 0; i < 16; ++i)
            cpa16(dst + tid + i*128, src + tid + i*128);
        cpa_commit();
    }
    __syncthreads();
    for (int l = tid; l < ESG*DD; l += 128) {
        int s = l >> 7, kk = l & 127;
        X[s][kk] = g_z1[(blk*ESG + s)*DD + kk] * A1[kk] + D1[kk];
    }
    cpa_wait0();
    __syncthreads();
    ull acc[8];
    #pragma unroll
    for (int i = 0; i < 8; ++i) acc[i] = 0ull;
    #pragma unroll 8
    for (int p = 0; p < DD/2; ++p) {
        ull wv = *(const ull*)&W2s[p*D2 + c];
        #pragma unroll
        for (int i = 0; i < 8; ++i) {
            ull x = *(const ull*)&X[h*8 + i][2*p];
            ffma2(acc[i], wv, x);
        }
    }
    float bb = b2[c];
    float lsum = 0.f, lss = 0.f;
    #pragma unroll
    for (int i = 0; i < 8; ++i) {
        float z = sum2(acc[i]) + bb;
        z = z > 0.f ? z : 0.f;
        g_z2[(blk*ESG + h*8 + i)*D2 + c] = z;
        lsum += z; lss += z*z;
    }
    atomicAdd(&g_s2[c], lsum);
    atomicAdd(&g_q2[c], lss);
}

__global__ void k_m2(const float* __restrict__ g2, const float* __restrict__ be2) {
    int c = threadIdx.x;  // 64
    float m = g_s2[c] * (1.0f/BB);
    float v = g_q2[c] * (1.0f/BB) - m*m;
    float r = rsqrtf(v + 1e-5f);
    float a = g2[c] * r;
    g_a2[c] = a;
    g_d2[c] = be2[c] - m*a;
}

// ---------------- pred = sigmoid(BN(z2) @ Wp^T + bp) -------------------------------
__global__ void k_pred(const float* __restrict__ Wp, const float* __restrict__ bp,
                       float* __restrict__ out_pred) {
    int warp = (blockIdx.x*blockDim.x + threadIdx.x) >> 5;
    int lane = threadIdx.x & 31;
    if (warp >= BB) return;
    float t = 0.f;
    #pragma unroll
    for (int j = 0; j < 2; ++j) {
        int cidx = lane + j*32;
        float f2 = g_z2[warp*D2 + cidx] * g_a2[cidx] + g_d2[cidx];
        t += f2 * Wp[cidx];
    }
    #pragma unroll
    for (int o = 16; o; o >>= 1) t += __shfl_down_sync(0xffffffffu, t, o);
    if (lane == 0) out_pred[warp] = 1.0f / (1.0f + expf(-(t + bp[0])));
}

// ---------------- launch ------------------------------------------------------------
extern "C" void kernel_launch(void* const* d_in, const int* in_sizes, int n_in,
                              void* d_out, int out_size) {
    const int*   nodes_u     = (const int*)  d_in[0];
    const int*   nodes_v     = (const int*)  d_in[1];
    const int*   nodes_d     = (const int*)  d_in[2];
    const int*   inter_items = (const int*)  d_in[3];
    const int*   top_n       = (const int*)  d_in[4];
    const float* protos      = (const float*)d_in[5];
    const float* pre_text    = (const float*)d_in[6];
    const float* pre_visual  = (const float*)d_in[7];
    const float* Wt          = (const float*)d_in[8];
    const float* bt          = (const float*)d_in[9];
    const float* Wv          = (const float*)d_in[10];
    const float* bv          = (const float*)d_in[11];
    const float* up          = (const float*)d_in[12];
    const float* ip          = (const float*)d_in[13];
    const float* dp          = (const float*)d_in[14];
    const float* W1          = (const float*)d_in[15];
    const float* b1          = (const float*)d_in[16];
    const float* g1          = (const float*)d_in[17];
    const float* be1         = (const float*)d_in[18];
    const float* W2          = (const float*)d_in[19];
    const float* b2          = (const float*)d_in[20];
    const float* g2          = (const float*)d_in[21];
    const float* be2         = (const float*)d_in[22];
    const float* Wp          = (const float*)d_in[23];
    const float* bp          = (const float*)d_in[24];

    float* out      = (float*)d_out;
    float* out_pred = out;
    float* out_pu   = out + BB;
    float* out_hu   = out + BB + BB*DD;
    float* out_pd   = out + BB + 2*BB*DD;

    cudaFuncSetAttribute(k_eh,  cudaFuncAttributeMaxDynamicSharedMemorySize, HU_SMEM);
    cudaFuncSetAttribute(k_z1m, cudaFuncAttributeMaxDynamicSharedMemorySize, HU_SMEM);

    k_prep<<<312, 256>>>(Wt, Wv, W1, W2, protos, bt, bv);
    k_xb<<<BB, 288>>>(nodes_v, pre_text, pre_visual);
    k_mask<<<BB, 128>>>(nodes_u, nodes_d, inter_items, top_n, up, dp, out_pu, out_pd);
    k_eh<<<256, 256, HU_SMEM>>>(nodes_v, ip, nodes_d, dp, out_hu);
    k_z1m<<<BB/32, 256, HU_SMEM>>>(b1);
    k_m1<<<1, 128>>>(g1, be1);
    k_z2<<<BB/ESG, 128>>>(b2);
    k_m2<<<1, 64>>>(g2, be2);
    k_pred<<<BB/8, 256>>>(Wp, bp, out_pred);
}